// round 10
// baseline (speedup 1.0000x reference)
#include <cuda_runtime.h>
#include <cuda_fp16.h>

#define NN 200000
#define EE 6400000
#define HH 16
#define CC 40
#define NBIN 512
#define ILV 16                      // ELL interleave: 16 nodes per warp-group
#define NG2 (NN / ILV)              // 12500 groups
#define NGB2 ((NG2 + 1023) / 1024)  // 13
#define EIL_CAP 7000000
#define DEPTH 4                     // cp.async pipeline depth

// ---------------- scratch (static device globals; no allocation) ----------------
__device__ int    g_cnt[NN];
__device__ float  g_dis[NN];        // node order (for k_xw)
__device__ float  g_disP[NN];       // rank order (for k_agg)
__device__ int    g_order[NN];      // rank -> node
__device__ int    g_rank[NN];       // node -> rank
__device__ int2   g_sbc[NN];        // .x cursor (atomic), .y slotbase
__device__ int    g_dbin[NBIN];
__device__ int    g_dcur[NBIN];
__device__ int    g_eil[EIL_CAP];   // x16-interleaved ELL, entries are RANKS
__device__ int    g_gmax[NG2];
__device__ int    g_gscan[NG2];
__device__ int    g_gbsum[NGB2];
__device__ int    g_gbase[NG2 + 1]; // slot base per group (int units)
// features fp16, RANK order, PRE-SCALED by dis; row NN is an always-zero pad row
__device__ __half g_hA[(NN + 1) * HH];
__device__ __half g_hB[(NN + 1) * HH];

// ---------------- prep ----------------
__global__ void k_zero() {
    int i = blockIdx.x * 256 + threadIdx.x;
    if (i < NN) { g_cnt[i] = 0; g_sbc[i].x = 0; }
    if (i < NBIN) { g_dbin[i] = 0; g_dcur[i] = 0; }
    if (i < 2) ((uint4*)g_hA)[NN * 2 + i] = make_uint4(0u, 0u, 0u, 0u);
    else if (i < 4) ((uint4*)g_hB)[NN * 2 + (i - 2)] = make_uint4(0u, 0u, 0u, 0u);
}

__global__ void k_hist(const int* __restrict__ ei) {  // 4 edges per thread
    int e4 = blockIdx.x * 256 + threadIdx.x;
    if (e4 < EE / 4) {
        int4 d = ((const int4*)(ei + EE))[e4];
        atomicAdd(&g_cnt[d.x], 1);
        atomicAdd(&g_cnt[d.y], 1);
        atomicAdd(&g_cnt[d.z], 1);
        atomicAdd(&g_cnt[d.w], 1);
    }
}

__global__ void k_dhist() {  // degree histogram + dis (fused)
    int i = blockIdx.x * 256 + threadIdx.x;
    if (i < NN) {
        int d = g_cnt[i];
        g_dis[i] = rsqrtf((float)(d + 1));
        if (d > NBIN - 1) d = NBIN - 1;
        atomicAdd(&g_dbin[d], 1);
    }
}

// place nodes into degree-sorted rank; each block redundantly scans the
// 512-bin histogram in SMEM (replaces the separate k_dscan launch)
__global__ void k_dplace() {
    __shared__ int pairsc[256];
    __shared__ int doff[NBIN];
    int t = threadIdx.x;
    int s0 = g_dbin[2 * t], s1 = g_dbin[2 * t + 1];
    pairsc[t] = s0 + s1;
    for (int off = 1; off < 256; off <<= 1) {
        __syncthreads();
        int u = (t >= off) ? pairsc[t - off] : 0;
        __syncthreads();
        pairsc[t] += u;
    }
    __syncthreads();
    int exp = pairsc[t] - (s0 + s1);   // exclusive pair prefix
    doff[2 * t] = exp;
    doff[2 * t + 1] = exp + s0;
    __syncthreads();

    int i = blockIdx.x * 256 + t;
    if (i < NN) {
        int d = g_cnt[i]; if (d > NBIN - 1) d = NBIN - 1;
        int p = doff[d] + atomicAdd(&g_dcur[d], 1);
        g_order[p] = i;
        g_rank[i] = p;
        g_disP[p] = g_dis[i];
    }
}

// fused: per-group max degree + 1024-wide inclusive scan of maxes
__global__ void k_gmaxscan() {
    __shared__ int sh[1024];
    int t = threadIdx.x;
    int i = blockIdx.x * 1024 + t;
    int m = 0;
    if (i < NG2) {
#pragma unroll
        for (int j = 0; j < ILV; j++) {
            int d = g_cnt[g_order[i * ILV + j]];
            m = d > m ? d : m;
        }
        g_gmax[i] = m;
    }
    sh[t] = m;
    for (int off = 1; off < 1024; off <<= 1) {
        __syncthreads();
        int u = (t >= off) ? sh[t - off] : 0;
        __syncthreads();
        sh[t] += u;
    }
    __syncthreads();
    if (i < NG2) g_gscan[i] = sh[t];
    if (t == 1023) g_gbsum[blockIdx.x] = sh[1023];
}

// fused: top-level scan (13 elems, redundant per block) + gbase + per-node
// slotbase + PRECISE ELL padding (only the slack slots)
__global__ void k_sbpad() {
    __shared__ int boff[NGB2 + 1];
    int t = threadIdx.x;
    if (t == 0) {
        int run = 0;
        for (int j = 0; j < NGB2; j++) { boff[j] = run; run += g_gbsum[j]; }
        boff[NGB2] = run;
    }
    __syncthreads();
    int i = blockIdx.x * 256 + t;
    if (i < NG2) {
        int ex = boff[i >> 10] + g_gscan[i] - g_gmax[i];
        g_gbase[i] = ex * ILV;
    }
    if (i == 0) g_gbase[NG2] = boff[NGB2] * ILV;
    if (i < NN) {
        int r = g_rank[i];
        int g = r >> 4;
        int gm = g_gmax[g];
        int base = (boff[g >> 10] + g_gscan[g] - gm) * ILV;
        int sb = base + (r & 15);
        g_sbc[i].y = sb;
        int deg = g_cnt[i];
        for (int k = deg; k < gm; k++) g_eil[sb + k * ILV] = NN;  // precise pad
    }
}

__global__ void k_scatter2(const int* __restrict__ ei) {  // 4 edges per thread
    int e4 = blockIdx.x * 256 + threadIdx.x;
    if (e4 < EE / 4) {
        int4 s = ((const int4*)ei)[e4];
        int4 d = ((const int4*)(ei + EE))[e4];
#pragma unroll
        for (int q = 0; q < 4; q++) {
            int ss = (q == 0) ? s.x : (q == 1) ? s.y : (q == 2) ? s.z : s.w;
            int dd = (q == 0) ? d.x : (q == 1) ? d.y : (q == 2) ? d.z : d.w;
            int i = atomicAdd(&g_sbc[dd].x, 1);
            int sb = g_sbc[dd].y;
            g_eil[sb + i * ILV] = g_rank[ss];
        }
    }
}

// -------- first transform: g_hA[rank(n)] = dis[n] * (x[n] @ w_in) --------
__global__ __launch_bounds__(256) void k_xw(const float* __restrict__ x,
                                            const float* __restrict__ w) {
    __shared__ float xs[16 * 128];
    __shared__ float ws[128 * 16];
    int t = threadIdx.x;
    for (int i = t; i < 2048; i += 256) ws[i] = w[i];
    const float* xb = x + (size_t)blockIdx.x * 2048;
    for (int i = t; i < 2048; i += 256) xs[i] = xb[i];
    __syncthreads();
    int ry = t >> 4, c = t & 15;
    float s = 0.f;
#pragma unroll
    for (int k = 0; k < 128; k++) s = fmaf(xs[ry * 128 + k], ws[k * 16 + c], s);
    int node = blockIdx.x * 16 + ry;
    g_hA[(size_t)g_rank[node] * 16 + c] = __float2half_rn(s * g_dis[node]);
}

// ---------------- cp.async helpers ----------------
__device__ __forceinline__ void cp16(unsigned smem, const void* gptr) {
    asm volatile("cp.async.cg.shared.global [%0], [%1], 16;"
                 :: "r"(smem), "l"(gptr) : "memory");
}
__device__ __forceinline__ void cp_commit() {
    asm volatile("cp.async.commit_group;" ::: "memory");
}
template <int N>
__device__ __forceinline__ void cp_wait() {
    asm volatile("cp.async.wait_group %0;" :: "n"(N) : "memory");
}

__device__ __forceinline__ void h8_init(float* a, uint4 v) {
    __half2* h = (__half2*)&v;
#pragma unroll
    for (int q = 0; q < 4; q++) {
        float2 f = __half22float2(h[q]);
        a[2 * q] = f.x; a[2 * q + 1] = f.y;
    }
}
__device__ __forceinline__ void h8_add(float* a, uint4 v) {
    __half2* h = (__half2*)&v;
#pragma unroll
    for (int q = 0; q < 4; q++) {
        float2 f = __half22float2(h[q]);
        a[2 * q] += f.x; a[2 * q + 1] += f.y;
    }
}
__device__ __forceinline__ uint4 f8_to_h8(const float* a) {
    uint4 r;
    __half2* h = (__half2*)&r;
#pragma unroll
    for (int q = 0; q < 4; q++) h[q] = __floats2half2_rn(a[2 * q], a[2 * q + 1]);
    return r;
}

// ---------------- fused aggregation layers (cp.async gather pipeline) -------
// MODE 0: h = relu(dis*agg+b); store dis*(h @ Wn)    [8x]
// MODE 1: store dis*relu(dis*agg+b)                   [h9]
// MODE 2: o = (dis*agg) @ w_out + b_out; log_softmax  [final]
template <int MODE>
__global__ __launch_bounds__(256) void k_agg(int inA,
                                             const float* __restrict__ preBias,
                                             const float* __restrict__ Wn,
                                             const float* __restrict__ postBias,
                                             float* __restrict__ fout) {
    __shared__ uint4 stage[8][DEPTH][32];
    __shared__ float wsh[640];
    __shared__ float bsh[40];
    __shared__ float hsh[128 * 17];
    int t = threadIdx.x;
    if (MODE == 0) wsh[t] = Wn[t & 255];
    if (MODE == 2) {
        for (int i = t; i < 640; i += 256) wsh[i] = Wn[i];
        if (t < 40) bsh[t] = postBias[t];
    }
    __syncthreads();

    int w = t >> 5, lane = t & 31;
    int gw = blockIdx.x * 8 + w;
    if (gw >= NG2) return;

    const uint4* tab = (const uint4*)(inA ? g_hA : g_hB);
    __half* outF = inA ? g_hB : g_hA;

    int j = lane >> 1, h = lane & 1;
    int row = gw * ILV + j;            // rank-ordered feature row
    float di = g_disP[row];

    float acc[8];
    h8_init(acc, __ldg(&tab[row * 2 + h]));   // self loop (coalesced)

    int base = g_gbase[gw];
    int nch = (g_gbase[gw + 1] - base) >> 4;
    const int* eilc = g_eil + base + j;
    unsigned sa0 = (unsigned)__cvta_generic_to_shared(&stage[w][0][lane]);

    int npro = nch < DEPTH ? nch : DEPTH;
    for (int c = 0; c < npro; c++) {
        int src = __ldg(eilc + c * ILV);
        cp16(sa0 + (c & (DEPTH - 1)) * 512, tab + src * 2 + h);
        cp_commit();
    }
    int c = 0;
    for (; c + DEPTH < nch; c++) {
        cp_wait<DEPTH - 1>();                       // buf c ready
        h8_add(acc, stage[w][c & (DEPTH - 1)][lane]);
        int cn = c + DEPTH;
        int src = __ldg(eilc + cn * ILV);
        cp16(sa0 + (cn & (DEPTH - 1)) * 512, tab + src * 2 + h);
        cp_commit();
    }
    cp_wait<0>();
    for (; c < nch; c++) h8_add(acc, stage[w][c & (DEPTH - 1)][lane]);

#pragma unroll
    for (int q = 0; q < 8; q++) acc[q] *= di;

    if (MODE != 2) {  // bias + relu
        const float* bp = preBias + h * 8;
#pragma unroll
        for (int q = 0; q < 8; q++) acc[q] = fmaxf(acc[q] + __ldg(bp + q), 0.f);
    }

    if (MODE == 1) {  // store dis*h (coalesced, rank order)
#pragma unroll
        for (int q = 0; q < 8; q++) acc[q] *= di;
        ((uint4*)outF)[row * 2 + h] = f8_to_h8(acc);
        return;
    }

    // share the node's 16-vector between its 2 lanes
    float* hr = &hsh[(t >> 1) * 17];
#pragma unroll
    for (int q = 0; q < 8; q++) hr[h * 8 + q] = acc[q];
    __syncwarp();

    if (MODE == 0) {  // 16x16 transform, store pre-scaled by dis
        float o[8];
#pragma unroll
        for (int jj = 0; jj < 8; jj++) {
            int col = h * 8 + jj;
            float s = 0.f;
#pragma unroll
            for (int k = 0; k < 16; k++) s = fmaf(hr[k], wsh[k * 16 + col], s);
            o[jj] = s * di;
        }
        ((uint4*)outF)[row * 2 + h] = f8_to_h8(o);
    } else {  // MODE 2: 16x40 output transform + log_softmax
        float o[20];
#pragma unroll
        for (int jj = 0; jj < 20; jj++) {
            int col = h * 20 + jj;
            float s = bsh[col];
#pragma unroll
            for (int k = 0; k < 16; k++) s = fmaf(hr[k], wsh[k * 40 + col], s);
            o[jj] = s;
        }
        float m = o[0];
#pragma unroll
        for (int jj = 1; jj < 20; jj++) m = fmaxf(m, o[jj]);
        m = fmaxf(m, __shfl_xor_sync(0xffffffffu, m, 1));
        float se = 0.f;
#pragma unroll
        for (int jj = 0; jj < 20; jj++) se += __expf(o[jj] - m);
        se += __shfl_xor_sync(0xffffffffu, se, 1);
        float l = m + __logf(se);
        int node = g_order[row];
#pragma unroll
        for (int jj = 0; jj < 20; jj++)
            fout[(size_t)node * 40 + h * 20 + jj] = o[jj] - l;
    }
}

// ---------------- launch ----------------
extern "C" void kernel_launch(void* const* d_in, const int* in_sizes, int n_in,
                              void* d_out, int out_size) {
    const float* x     = (const float*)d_in[0];
    const float* w_in  = (const float*)d_in[1];
    const float* b_in  = (const float*)d_in[2];
    const float* w_hid = (const float*)d_in[3];
    const float* b_hid = (const float*)d_in[4];
    const float* w_out = (const float*)d_in[5];
    const float* b_out = (const float*)d_in[6];
    const int*   ei    = (const int*)d_in[7];
    float* out = (float*)d_out;

    const int NB_N = (NN + 255) / 256;    // 782
    const int NB_E4 = (EE / 4 + 255) / 256;  // 6250
    const int NB_A = (NG2 + 7) / 8;       // 1563

    // prep: counts -> degree sort -> group bases (+precise pad) -> ELL scatter
    k_zero<<<NB_N, 256>>>();
    k_hist<<<NB_E4, 256>>>(ei);
    k_dhist<<<NB_N, 256>>>();
    k_dplace<<<NB_N, 256>>>();
    k_gmaxscan<<<NGB2, 1024>>>();
    k_sbpad<<<NB_N, 256>>>();
    k_scatter2<<<NB_E4, 256>>>(ei);

    // t0-hat = dis * (x @ w_in)  -> g_hA (rank order)
    k_xw<<<NN / 16, 256>>>(x, w_in);

    // layers 1..8: fused agg + bias + relu + next 16x16 transform (ping-pong)
    k_agg<0><<<NB_A, 256>>>(1, b_in,         w_hid + 0 * 256, nullptr, nullptr);
    k_agg<0><<<NB_A, 256>>>(0, b_hid + 0*16, w_hid + 1 * 256, nullptr, nullptr);
    k_agg<0><<<NB_A, 256>>>(1, b_hid + 1*16, w_hid + 2 * 256, nullptr, nullptr);
    k_agg<0><<<NB_A, 256>>>(0, b_hid + 2*16, w_hid + 3 * 256, nullptr, nullptr);
    k_agg<0><<<NB_A, 256>>>(1, b_hid + 3*16, w_hid + 4 * 256, nullptr, nullptr);
    k_agg<0><<<NB_A, 256>>>(0, b_hid + 4*16, w_hid + 5 * 256, nullptr, nullptr);
    k_agg<0><<<NB_A, 256>>>(1, b_hid + 5*16, w_hid + 6 * 256, nullptr, nullptr);
    k_agg<0><<<NB_A, 256>>>(0, b_hid + 6*16, w_hid + 7 * 256, nullptr, nullptr);
    // layer 9: h9-hat (hA -> hB)
    k_agg<1><<<NB_A, 256>>>(1, b_hid + 7*16, nullptr, nullptr, nullptr);
    // layer 10: out = log_softmax((dis*agg(h9-hat)) @ w_out + b_out)
    k_agg<2><<<NB_A, 256>>>(0, nullptr, w_out, b_out, out);
}

// round 12
// speedup vs baseline: 1.1053x; 1.1053x over previous
#include <cuda_runtime.h>
#include <cuda_fp16.h>

#define NN 200000
#define EE 6400000
#define HH 16
#define CC 40
#define NBIN 512
#define ILV 16                      // ELL interleave: 16 nodes per warp-group
#define NG2 (NN / ILV)              // 12500 groups
#define NGB2 ((NG2 + 1023) / 1024)  // 13
#define EIL_CAP 7000000
#define DEPTH 4                     // cp.async pipeline depth

// ---------------- scratch (static device globals; no allocation) ----------------
__device__ int    g_cnt[NN];
__device__ float  g_dis[NN];        // node order (for k_xw)
__device__ float  g_disP[NN];       // rank order (for k_agg)
__device__ int    g_order[NN];      // rank -> node
__device__ int    g_rank[NN];       // node -> rank
__device__ int2   g_sbc[NN];        // .x cursor (atomic), .y slotbase
__device__ int    g_dbin[NBIN];
__device__ int    g_dcur[NBIN];
__device__ int    g_eil[EIL_CAP];   // x16-interleaved ELL, entries are RANKS
__device__ int    g_gmax[NG2];
__device__ int    g_gscan[NG2];
__device__ int    g_gbsum[NGB2];
__device__ int    g_gbase[NG2 + 1]; // slot base per group (int units)
// features fp16, RANK order, PRE-SCALED by dis; row NN is an always-zero pad row
__device__ __half g_hA[(NN + 1) * HH];
__device__ __half g_hB[(NN + 1) * HH];

// ---------------- prep ----------------
__global__ void k_zero() {
    int i = blockIdx.x * 256 + threadIdx.x;
    if (i < NN) { g_cnt[i] = 0; g_sbc[i].x = 0; }
    if (i < NBIN) { g_dbin[i] = 0; g_dcur[i] = 0; }
    if (i < 2) ((uint4*)g_hA)[NN * 2 + i] = make_uint4(0u, 0u, 0u, 0u);
    else if (i < 4) ((uint4*)g_hB)[NN * 2 + (i - 2)] = make_uint4(0u, 0u, 0u, 0u);
}

__global__ void k_hist(const int* __restrict__ ei) {  // 4 edges per thread
    int e4 = blockIdx.x * 256 + threadIdx.x;
    if (e4 < EE / 4) {
        int4 d = ((const int4*)(ei + EE))[e4];
        atomicAdd(&g_cnt[d.x], 1);
        atomicAdd(&g_cnt[d.y], 1);
        atomicAdd(&g_cnt[d.z], 1);
        atomicAdd(&g_cnt[d.w], 1);
    }
}

// degree histogram + dis; SMEM-aggregated atomics (hot bins ~14K nodes)
__global__ void k_dhist() {
    __shared__ int sh[NBIN];
    int t = threadIdx.x;
    sh[t] = 0; sh[t + 256] = 0;
    __syncthreads();
    int i = blockIdx.x * 256 + t;
    if (i < NN) {
        int d = g_cnt[i];
        g_dis[i] = rsqrtf((float)(d + 1));
        if (d > NBIN - 1) d = NBIN - 1;
        atomicAdd(&sh[d], 1);
    }
    __syncthreads();
    if (sh[t]) atomicAdd(&g_dbin[t], sh[t]);
    if (sh[t + 256]) atomicAdd(&g_dbin[t + 256], sh[t + 256]);
}

// degree-sorted rank placement; per-block SMEM aggregation: one global
// atomic per (block, bin) instead of one per node
__global__ void k_dplace() {
    __shared__ int pairsc[256];
    __shared__ int doff[NBIN];
    __shared__ int lcnt[NBIN];
    __shared__ int lbase[NBIN];
    int t = threadIdx.x;
    // redundant per-block scan of the global degree histogram -> doff
    int s0 = g_dbin[2 * t], s1 = g_dbin[2 * t + 1];
    pairsc[t] = s0 + s1;
    lcnt[2 * t] = 0; lcnt[2 * t + 1] = 0;
    for (int off = 1; off < 256; off <<= 1) {
        __syncthreads();
        int u = (t >= off) ? pairsc[t - off] : 0;
        __syncthreads();
        pairsc[t] += u;
    }
    __syncthreads();
    int exp = pairsc[t] - (s0 + s1);   // exclusive pair prefix
    doff[2 * t] = exp;
    doff[2 * t + 1] = exp + s0;
    __syncthreads();

    int i = blockIdx.x * 256 + t;
    int d = -1, lo = 0;
    if (i < NN) {
        d = g_cnt[i]; if (d > NBIN - 1) d = NBIN - 1;
        lo = atomicAdd(&lcnt[d], 1);       // in-block offset (SMEM, fast)
    }
    __syncthreads();
    if (lcnt[2 * t]) lbase[2 * t] = atomicAdd(&g_dcur[2 * t], lcnt[2 * t]);
    if (lcnt[2 * t + 1]) lbase[2 * t + 1] = atomicAdd(&g_dcur[2 * t + 1], lcnt[2 * t + 1]);
    __syncthreads();
    if (i < NN) {
        int p = doff[d] + lbase[d] + lo;
        g_order[p] = i;
        g_rank[i] = p;
        g_disP[p] = g_dis[i];
    }
}

// fused: per-group max degree + 1024-wide inclusive scan of maxes
__global__ void k_gmaxscan() {
    __shared__ int sh[1024];
    int t = threadIdx.x;
    int i = blockIdx.x * 1024 + t;
    int m = 0;
    if (i < NG2) {
#pragma unroll
        for (int j = 0; j < ILV; j++) {
            int d = g_cnt[g_order[i * ILV + j]];
            m = d > m ? d : m;
        }
        g_gmax[i] = m;
    }
    sh[t] = m;
    for (int off = 1; off < 1024; off <<= 1) {
        __syncthreads();
        int u = (t >= off) ? sh[t - off] : 0;
        __syncthreads();
        sh[t] += u;
    }
    __syncthreads();
    if (i < NG2) g_gscan[i] = sh[t];
    if (t == 1023) g_gbsum[blockIdx.x] = sh[1023];
}

// fused: top-level scan (13 elems, redundant per block) + gbase + per-node
// slotbase + PRECISE ELL padding (only the slack slots)
__global__ void k_sbpad() {
    __shared__ int boff[NGB2 + 1];
    int t = threadIdx.x;
    if (t == 0) {
        int run = 0;
        for (int j = 0; j < NGB2; j++) { boff[j] = run; run += g_gbsum[j]; }
        boff[NGB2] = run;
    }
    __syncthreads();
    int i = blockIdx.x * 256 + t;
    if (i < NG2) {
        int ex = boff[i >> 10] + g_gscan[i] - g_gmax[i];
        g_gbase[i] = ex * ILV;
    }
    if (i == 0) g_gbase[NG2] = boff[NGB2] * ILV;
    if (i < NN) {
        int r = g_rank[i];
        int g = r >> 4;
        int gm = g_gmax[g];
        int base = (boff[g >> 10] + g_gscan[g] - gm) * ILV;
        int sb = base + (r & 15);
        g_sbc[i].y = sb;
        int deg = g_cnt[i];
        for (int k = deg; k < gm; k++) g_eil[sb + k * ILV] = NN;  // precise pad
    }
}

__global__ void k_scatter2(const int* __restrict__ ei) {  // 4 edges per thread
    int e4 = blockIdx.x * 256 + threadIdx.x;
    if (e4 < EE / 4) {
        int4 s = ((const int4*)ei)[e4];
        int4 d = ((const int4*)(ei + EE))[e4];
#pragma unroll
        for (int q = 0; q < 4; q++) {
            int ss = (q == 0) ? s.x : (q == 1) ? s.y : (q == 2) ? s.z : s.w;
            int dd = (q == 0) ? d.x : (q == 1) ? d.y : (q == 2) ? d.z : d.w;
            int i = atomicAdd(&g_sbc[dd].x, 1);
            int sb = g_sbc[dd].y;
            g_eil[sb + i * ILV] = g_rank[ss];
        }
    }
}

// -------- first transform: g_hA[rank(n)] = dis[n] * (x[n] @ w_in) --------
__global__ __launch_bounds__(256) void k_xw(const float* __restrict__ x,
                                            const float* __restrict__ w) {
    __shared__ float xs[16 * 128];
    __shared__ float ws[128 * 16];
    int t = threadIdx.x;
    for (int i = t; i < 2048; i += 256) ws[i] = w[i];
    const float* xb = x + (size_t)blockIdx.x * 2048;
    for (int i = t; i < 2048; i += 256) xs[i] = xb[i];
    __syncthreads();
    int ry = t >> 4, c = t & 15;
    float s = 0.f;
#pragma unroll
    for (int k = 0; k < 128; k++) s = fmaf(xs[ry * 128 + k], ws[k * 16 + c], s);
    int node = blockIdx.x * 16 + ry;
    g_hA[(size_t)g_rank[node] * 16 + c] = __float2half_rn(s * g_dis[node]);
}

// ---------------- cp.async helpers ----------------
__device__ __forceinline__ void cp16(unsigned smem, const void* gptr) {
    asm volatile("cp.async.cg.shared.global [%0], [%1], 16;"
                 :: "r"(smem), "l"(gptr) : "memory");
}
__device__ __forceinline__ void cp_commit() {
    asm volatile("cp.async.commit_group;" ::: "memory");
}
template <int N>
__device__ __forceinline__ void cp_wait() {
    asm volatile("cp.async.wait_group %0;" :: "n"(N) : "memory");
}

__device__ __forceinline__ void h8_init(float* a, uint4 v) {
    __half2* h = (__half2*)&v;
#pragma unroll
    for (int q = 0; q < 4; q++) {
        float2 f = __half22float2(h[q]);
        a[2 * q] = f.x; a[2 * q + 1] = f.y;
    }
}
__device__ __forceinline__ void h8_add(float* a, uint4 v) {
    __half2* h = (__half2*)&v;
#pragma unroll
    for (int q = 0; q < 4; q++) {
        float2 f = __half22float2(h[q]);
        a[2 * q] += f.x; a[2 * q + 1] += f.y;
    }
}
__device__ __forceinline__ uint4 f8_to_h8(const float* a) {
    uint4 r;
    __half2* h = (__half2*)&r;
#pragma unroll
    for (int q = 0; q < 4; q++) h[q] = __floats2half2_rn(a[2 * q], a[2 * q + 1]);
    return r;
}

// ---------------- fused aggregation layers (cp.async gather pipeline) -------
// MODE 0: h = relu(dis*agg+b); store dis*(h @ Wn)    [8x]
// MODE 1: store dis*relu(dis*agg+b)                   [h9]
// MODE 2: o = (dis*agg) @ w_out + b_out; log_softmax  [final]
template <int MODE>
__global__ __launch_bounds__(256) void k_agg(int inA,
                                             const float* __restrict__ preBias,
                                             const float* __restrict__ Wn,
                                             const float* __restrict__ postBias,
                                             float* __restrict__ fout) {
    __shared__ uint4 stage[8][DEPTH][32];
    __shared__ float wsh[640];
    __shared__ float bsh[40];
    __shared__ float hsh[128 * 17];
    int t = threadIdx.x;
    if (MODE == 0) wsh[t] = Wn[t & 255];
    if (MODE == 2) {
        for (int i = t; i < 640; i += 256) wsh[i] = Wn[i];
        if (t < 40) bsh[t] = postBias[t];
    }
    __syncthreads();

    int w = t >> 5, lane = t & 31;
    int gw = blockIdx.x * 8 + w;
    if (gw >= NG2) return;

    const uint4* tab = (const uint4*)(inA ? g_hA : g_hB);
    __half* outF = inA ? g_hB : g_hA;

    int j = lane >> 1, h = lane & 1;
    int row = gw * ILV + j;            // rank-ordered feature row
    float di = g_disP[row];

    float acc[8];
    h8_init(acc, __ldg(&tab[row * 2 + h]));   // self loop (coalesced)

    int base = g_gbase[gw];
    int nch = (g_gbase[gw + 1] - base) >> 4;
    const int* eilc = g_eil + base + j;
    unsigned sa0 = (unsigned)__cvta_generic_to_shared(&stage[w][0][lane]);

    int npro = nch < DEPTH ? nch : DEPTH;
    for (int c = 0; c < npro; c++) {
        int src = __ldg(eilc + c * ILV);
        cp16(sa0 + (c & (DEPTH - 1)) * 512, tab + src * 2 + h);
        cp_commit();
    }
    int c = 0;
    for (; c + DEPTH < nch; c++) {
        cp_wait<DEPTH - 1>();                       // buf c ready
        h8_add(acc, stage[w][c & (DEPTH - 1)][lane]);
        int cn = c + DEPTH;
        int src = __ldg(eilc + cn * ILV);
        cp16(sa0 + (cn & (DEPTH - 1)) * 512, tab + src * 2 + h);
        cp_commit();
    }
    cp_wait<0>();
    for (; c < nch; c++) h8_add(acc, stage[w][c & (DEPTH - 1)][lane]);

#pragma unroll
    for (int q = 0; q < 8; q++) acc[q] *= di;

    if (MODE != 2) {  // bias + relu
        const float* bp = preBias + h * 8;
#pragma unroll
        for (int q = 0; q < 8; q++) acc[q] = fmaxf(acc[q] + __ldg(bp + q), 0.f);
    }

    if (MODE == 1) {  // store dis*h (coalesced, rank order)
#pragma unroll
        for (int q = 0; q < 8; q++) acc[q] *= di;
        ((uint4*)outF)[row * 2 + h] = f8_to_h8(acc);
        return;
    }

    // share the node's 16-vector between its 2 lanes
    float* hr = &hsh[(t >> 1) * 17];
#pragma unroll
    for (int q = 0; q < 8; q++) hr[h * 8 + q] = acc[q];
    __syncwarp();

    if (MODE == 0) {  // 16x16 transform, store pre-scaled by dis
        float o[8];
#pragma unroll
        for (int jj = 0; jj < 8; jj++) {
            int col = h * 8 + jj;
            float s = 0.f;
#pragma unroll
            for (int k = 0; k < 16; k++) s = fmaf(hr[k], wsh[k * 16 + col], s);
            o[jj] = s * di;
        }
        ((uint4*)outF)[row * 2 + h] = f8_to_h8(o);
    } else {  // MODE 2: 16x40 output transform + log_softmax
        float o[20];
#pragma unroll
        for (int jj = 0; jj < 20; jj++) {
            int col = h * 20 + jj;
            float s = bsh[col];
#pragma unroll
            for (int k = 0; k < 16; k++) s = fmaf(hr[k], wsh[k * 40 + col], s);
            o[jj] = s;
        }
        float m = o[0];
#pragma unroll
        for (int jj = 1; jj < 20; jj++) m = fmaxf(m, o[jj]);
        m = fmaxf(m, __shfl_xor_sync(0xffffffffu, m, 1));
        float se = 0.f;
#pragma unroll
        for (int jj = 0; jj < 20; jj++) se += __expf(o[jj] - m);
        se += __shfl_xor_sync(0xffffffffu, se, 1);
        float l = m + __logf(se);
        int node = g_order[row];
#pragma unroll
        for (int jj = 0; jj < 20; jj++)
            fout[(size_t)node * 40 + h * 20 + jj] = o[jj] - l;
    }
}

// ---------------- launch ----------------
extern "C" void kernel_launch(void* const* d_in, const int* in_sizes, int n_in,
                              void* d_out, int out_size) {
    const float* x     = (const float*)d_in[0];
    const float* w_in  = (const float*)d_in[1];
    const float* b_in  = (const float*)d_in[2];
    const float* w_hid = (const float*)d_in[3];
    const float* b_hid = (const float*)d_in[4];
    const float* w_out = (const float*)d_in[5];
    const float* b_out = (const float*)d_in[6];
    const int*   ei    = (const int*)d_in[7];
    float* out = (float*)d_out;

    const int NB_N = (NN + 255) / 256;       // 782
    const int NB_E4 = (EE / 4 + 255) / 256;  // 6250
    const int NB_A = (NG2 + 7) / 8;          // 1563

    // prep: counts -> degree sort -> group bases (+precise pad) -> ELL scatter
    k_zero<<<NB_N, 256>>>();
    k_hist<<<NB_E4, 256>>>(ei);
    k_dhist<<<NB_N, 256>>>();
    k_dplace<<<NB_N, 256>>>();
    k_gmaxscan<<<NGB2, 1024>>>();
    k_sbpad<<<NB_N, 256>>>();
    k_scatter2<<<NB_E4, 256>>>(ei);

    // t0-hat = dis * (x @ w_in)  -> g_hA (rank order)
    k_xw<<<NN / 16, 256>>>(x, w_in);

    // layers 1..8: fused agg + bias + relu + next 16x16 transform (ping-pong)
    k_agg<0><<<NB_A, 256>>>(1, b_in,         w_hid + 0 * 256, nullptr, nullptr);
    k_agg<0><<<NB_A, 256>>>(0, b_hid + 0*16, w_hid + 1 * 256, nullptr, nullptr);
    k_agg<0><<<NB_A, 256>>>(1, b_hid + 1*16, w_hid + 2 * 256, nullptr, nullptr);
    k_agg<0><<<NB_A, 256>>>(0, b_hid + 2*16, w_hid + 3 * 256, nullptr, nullptr);
    k_agg<0><<<NB_A, 256>>>(1, b_hid + 3*16, w_hid + 4 * 256, nullptr, nullptr);
    k_agg<0><<<NB_A, 256>>>(0, b_hid + 4*16, w_hid + 5 * 256, nullptr, nullptr);
    k_agg<0><<<NB_A, 256>>>(1, b_hid + 5*16, w_hid + 6 * 256, nullptr, nullptr);
    k_agg<0><<<NB_A, 256>>>(0, b_hid + 6*16, w_hid + 7 * 256, nullptr, nullptr);
    // layer 9: h9-hat (hA -> hB)
    k_agg<1><<<NB_A, 256>>>(1, b_hid + 7*16, nullptr, nullptr, nullptr);
    // layer 10: out = log_softmax((dis*agg(h9-hat)) @ w_out + b_out)
    k_agg<2><<<NB_A, 256>>>(0, nullptr, w_out, b_out, out);
}

// round 13
// speedup vs baseline: 1.1155x; 1.0093x over previous
#include <cuda_runtime.h>
#include <cuda_fp16.h>

#define NN 200000
#define EE 6400000
#define HH 16
#define CC 40
#define NBIN 512
#define ILV 16                      // ELL interleave: 16 nodes per warp-group
#define NG2 (NN / ILV)              // 12500 groups
#define NGB2 ((NG2 + 1023) / 1024)  // 13
#define EIL_CAP 7000000
#define DEPTH 4                     // cp.async pipeline depth
#define NBA 1563                    // agg grid (ceil(NG2/8))
#define BPERM 997                   // block permutation, coprime to 1563=3*521

// ---------------- scratch (static device globals; no allocation) ----------------
__device__ int    g_cnt[NN];
__device__ float  g_dis[NN];        // node order (for k_xw)
__device__ float  g_disP[NN];       // rank order (for k_agg)
__device__ int    g_order[NN];      // rank -> node
__device__ int    g_rank[NN];       // node -> rank
__device__ int2   g_sbc[NN];        // .x cursor (atomic), .y slotbase
__device__ int    g_dbin[NBIN];
__device__ int    g_dcur[NBIN];
__device__ int    g_eil[EIL_CAP];   // x16-interleaved ELL, entries are RANKS
__device__ int    g_gmax[NG2];
__device__ int    g_gscan[NG2];
__device__ int    g_gbsum[NGB2];
__device__ int    g_gbase[NG2 + 1]; // slot base per group (int units)
// features fp16, RANK order, PRE-SCALED by dis; row NN is an always-zero pad row
__device__ __half g_hA[(NN + 1) * HH];
__device__ __half g_hB[(NN + 1) * HH];

// ---------------- prep ----------------
__global__ void k_zero() {
    int i = blockIdx.x * 256 + threadIdx.x;
    if (i < NN) { g_cnt[i] = 0; g_sbc[i].x = 0; }
    if (i < NBIN) { g_dbin[i] = 0; g_dcur[i] = 0; }
    if (i < 2) ((uint4*)g_hA)[NN * 2 + i] = make_uint4(0u, 0u, 0u, 0u);
    else if (i < 4) ((uint4*)g_hB)[NN * 2 + (i - 2)] = make_uint4(0u, 0u, 0u, 0u);
}

__global__ void k_hist(const int* __restrict__ ei) {  // 4 edges per thread
    int e4 = blockIdx.x * 256 + threadIdx.x;
    if (e4 < EE / 4) {
        int4 d = ((const int4*)(ei + EE))[e4];
        atomicAdd(&g_cnt[d.x], 1);
        atomicAdd(&g_cnt[d.y], 1);
        atomicAdd(&g_cnt[d.z], 1);
        atomicAdd(&g_cnt[d.w], 1);
    }
}

// degree histogram + dis; SMEM-aggregated atomics
__global__ void k_dhist() {
    __shared__ int sh[NBIN];
    int t = threadIdx.x;
    sh[t] = 0; sh[t + 256] = 0;
    __syncthreads();
    int i = blockIdx.x * 256 + t;
    if (i < NN) {
        int d = g_cnt[i];
        g_dis[i] = rsqrtf((float)(d + 1));
        if (d > NBIN - 1) d = NBIN - 1;
        atomicAdd(&sh[d], 1);
    }
    __syncthreads();
    if (sh[t]) atomicAdd(&g_dbin[t], sh[t]);
    if (sh[t + 256]) atomicAdd(&g_dbin[t + 256], sh[t + 256]);
}

// degree-sorted rank placement; per-block SMEM aggregation
__global__ void k_dplace() {
    __shared__ int pairsc[256];
    __shared__ int doff[NBIN];
    __shared__ int lcnt[NBIN];
    __shared__ int lbase[NBIN];
    int t = threadIdx.x;
    int s0 = g_dbin[2 * t], s1 = g_dbin[2 * t + 1];
    pairsc[t] = s0 + s1;
    lcnt[2 * t] = 0; lcnt[2 * t + 1] = 0;
    for (int off = 1; off < 256; off <<= 1) {
        __syncthreads();
        int u = (t >= off) ? pairsc[t - off] : 0;
        __syncthreads();
        pairsc[t] += u;
    }
    __syncthreads();
    int exp = pairsc[t] - (s0 + s1);   // exclusive pair prefix
    doff[2 * t] = exp;
    doff[2 * t + 1] = exp + s0;
    __syncthreads();

    int i = blockIdx.x * 256 + t;
    int d = -1, lo = 0;
    if (i < NN) {
        d = g_cnt[i]; if (d > NBIN - 1) d = NBIN - 1;
        lo = atomicAdd(&lcnt[d], 1);       // in-block offset (SMEM, fast)
    }
    __syncthreads();
    if (lcnt[2 * t]) lbase[2 * t] = atomicAdd(&g_dcur[2 * t], lcnt[2 * t]);
    if (lcnt[2 * t + 1]) lbase[2 * t + 1] = atomicAdd(&g_dcur[2 * t + 1], lcnt[2 * t + 1]);
    __syncthreads();
    if (i < NN) {
        int p = doff[d] + lbase[d] + lo;
        g_order[p] = i;
        g_rank[i] = p;
        g_disP[p] = g_dis[i];
    }
}

// fused: per-group max degree + 1024-wide inclusive scan of maxes
__global__ void k_gmaxscan() {
    __shared__ int sh[1024];
    int t = threadIdx.x;
    int i = blockIdx.x * 1024 + t;
    int m = 0;
    if (i < NG2) {
#pragma unroll
        for (int j = 0; j < ILV; j++) {
            int d = g_cnt[g_order[i * ILV + j]];
            m = d > m ? d : m;
        }
        g_gmax[i] = m;
    }
    sh[t] = m;
    for (int off = 1; off < 1024; off <<= 1) {
        __syncthreads();
        int u = (t >= off) ? sh[t - off] : 0;
        __syncthreads();
        sh[t] += u;
    }
    __syncthreads();
    if (i < NG2) g_gscan[i] = sh[t];
    if (t == 1023) g_gbsum[blockIdx.x] = sh[1023];
}

// fused: top-level scan + gbase + per-node slotbase + PRECISE ELL padding
__global__ void k_sbpad() {
    __shared__ int boff[NGB2 + 1];
    int t = threadIdx.x;
    if (t == 0) {
        int run = 0;
        for (int j = 0; j < NGB2; j++) { boff[j] = run; run += g_gbsum[j]; }
        boff[NGB2] = run;
    }
    __syncthreads();
    int i = blockIdx.x * 256 + t;
    if (i < NG2) {
        int ex = boff[i >> 10] + g_gscan[i] - g_gmax[i];
        g_gbase[i] = ex * ILV;
    }
    if (i == 0) g_gbase[NG2] = boff[NGB2] * ILV;
    if (i < NN) {
        int r = g_rank[i];
        int g = r >> 4;
        int gm = g_gmax[g];
        int base = (boff[g >> 10] + g_gscan[g] - gm) * ILV;
        int sb = base + (r & 15);
        g_sbc[i].y = sb;
        int deg = g_cnt[i];
        for (int k = deg; k < gm; k++) g_eil[sb + k * ILV] = NN;  // precise pad
    }
}

__global__ void k_scatter2(const int* __restrict__ ei) {  // 4 edges per thread
    int e4 = blockIdx.x * 256 + threadIdx.x;
    if (e4 < EE / 4) {
        int4 s = ((const int4*)ei)[e4];
        int4 d = ((const int4*)(ei + EE))[e4];
#pragma unroll
        for (int q = 0; q < 4; q++) {
            int ss = (q == 0) ? s.x : (q == 1) ? s.y : (q == 2) ? s.z : s.w;
            int dd = (q == 0) ? d.x : (q == 1) ? d.y : (q == 2) ? d.z : d.w;
            int i = atomicAdd(&g_sbc[dd].x, 1);
            int sb = g_sbc[dd].y;
            g_eil[sb + i * ILV] = g_rank[ss];
        }
    }
}

// -------- first transform: g_hA[rank(n)] = dis[n] * (x[n] @ w_in) --------
__global__ __launch_bounds__(256) void k_xw(const float* __restrict__ x,
                                            const float* __restrict__ w) {
    __shared__ float xs[16 * 128];
    __shared__ float ws[128 * 16];
    int t = threadIdx.x;
    for (int i = t; i < 2048; i += 256) ws[i] = w[i];
    const float* xb = x + (size_t)blockIdx.x * 2048;
    for (int i = t; i < 2048; i += 256) xs[i] = xb[i];
    __syncthreads();
    int ry = t >> 4, c = t & 15;
    float s = 0.f;
#pragma unroll
    for (int k = 0; k < 128; k++) s = fmaf(xs[ry * 128 + k], ws[k * 16 + c], s);
    int node = blockIdx.x * 16 + ry;
    g_hA[(size_t)g_rank[node] * 16 + c] = __float2half_rn(s * g_dis[node]);
}

// ---------------- cp.async helpers ----------------
__device__ __forceinline__ void cp16(unsigned smem, const void* gptr) {
    asm volatile("cp.async.cg.shared.global [%0], [%1], 16;"
                 :: "r"(smem), "l"(gptr) : "memory");
}
__device__ __forceinline__ void cp_commit() {
    asm volatile("cp.async.commit_group;" ::: "memory");
}
template <int N>
__device__ __forceinline__ void cp_wait() {
    asm volatile("cp.async.wait_group %0;" :: "n"(N) : "memory");
}

__device__ __forceinline__ void h8_init(float* a, uint4 v) {
    __half2* h = (__half2*)&v;
#pragma unroll
    for (int q = 0; q < 4; q++) {
        float2 f = __half22float2(h[q]);
        a[2 * q] = f.x; a[2 * q + 1] = f.y;
    }
}
__device__ __forceinline__ void h8_add(float* a, uint4 v) {
    __half2* h = (__half2*)&v;
#pragma unroll
    for (int q = 0; q < 4; q++) {
        float2 f = __half22float2(h[q]);
        a[2 * q] += f.x; a[2 * q + 1] += f.y;
    }
}
__device__ __forceinline__ uint4 f8_to_h8(const float* a) {
    uint4 r;
    __half2* h = (__half2*)&r;
#pragma unroll
    for (int q = 0; q < 4; q++) h[q] = __floats2half2_rn(a[2 * q], a[2 * q + 1]);
    return r;
}

// ---------------- fused aggregation layers (cp.async gather pipeline) -------
// MODE 0: h = relu(dis*agg+b); store dis*(h @ Wn)    [8x]
// MODE 1: store dis*relu(dis*agg+b)                   [h9]
// MODE 2: o = (dis*agg) @ w_out + b_out; log_softmax  [final]
template <int MODE>
__global__ __launch_bounds__(256) void k_agg(int inA,
                                             const float* __restrict__ preBias,
                                             const float* __restrict__ Wn,
                                             const float* __restrict__ postBias,
                                             float* __restrict__ fout) {
    __shared__ uint4 stage[8][DEPTH][32];
    __shared__ float wsh[640];
    __shared__ float bsh[40];
    __shared__ float hsh[128 * 17];
    int t = threadIdx.x;
    if (MODE == 0) wsh[t] = Wn[t & 255];
    if (MODE == 2) {
        for (int i = t; i < 640; i += 256) wsh[i] = Wn[i];
        if (t < 40) bsh[t] = postBias[t];
    }
    __syncthreads();

    int w = t >> 5, lane = t & 31;
    // block-level degree swizzle: spreads the degree-sorted work across
    // SMs/waves; warps within a block keep near-uniform degree
    int b = (int)(((long long)blockIdx.x * BPERM) % NBA);
    int gw = b * 8 + w;
    if (gw >= NG2) return;

    const uint4* tab = (const uint4*)(inA ? g_hA : g_hB);
    __half* outF = inA ? g_hB : g_hA;

    int j = lane >> 1, h = lane & 1;
    int row = gw * ILV + j;            // rank-ordered feature row
    float di = g_disP[row];

    float acc[8];
    h8_init(acc, __ldg(&tab[row * 2 + h]));   // self loop (coalesced)

    int base = g_gbase[gw];
    int nch = (g_gbase[gw + 1] - base) >> 4;
    const int* eilc = g_eil + base + j;
    unsigned sa0 = (unsigned)__cvta_generic_to_shared(&stage[w][0][lane]);

    int npro = nch < DEPTH ? nch : DEPTH;
    for (int c = 0; c < npro; c++) {
        int src = __ldg(eilc + c * ILV);
        cp16(sa0 + (c & (DEPTH - 1)) * 512, tab + src * 2 + h);
        cp_commit();
    }
    int c = 0;
    // steady state: consume 2 chunks per wait, issue 2
    for (; c + DEPTH + 1 < nch; c += 2) {
        cp_wait<DEPTH - 2>();                       // chunks c, c+1 ready
        h8_add(acc, stage[w][c & (DEPTH - 1)][lane]);
        h8_add(acc, stage[w][(c + 1) & (DEPTH - 1)][lane]);
        int c0 = c + DEPTH, c1 = c + DEPTH + 1;
        int s0 = __ldg(eilc + c0 * ILV);
        int s1 = __ldg(eilc + c1 * ILV);
        cp16(sa0 + (c0 & (DEPTH - 1)) * 512, tab + s0 * 2 + h);
        cp_commit();
        cp16(sa0 + (c1 & (DEPTH - 1)) * 512, tab + s1 * 2 + h);
        cp_commit();
    }
    cp_wait<0>();
    for (; c < nch; c++) h8_add(acc, stage[w][c & (DEPTH - 1)][lane]);

#pragma unroll
    for (int q = 0; q < 8; q++) acc[q] *= di;

    if (MODE != 2) {  // bias + relu
        const float* bp = preBias + h * 8;
#pragma unroll
        for (int q = 0; q < 8; q++) acc[q] = fmaxf(acc[q] + __ldg(bp + q), 0.f);
    }

    if (MODE == 1) {  // store dis*h (coalesced, rank order)
#pragma unroll
        for (int q = 0; q < 8; q++) acc[q] *= di;
        ((uint4*)outF)[row * 2 + h] = f8_to_h8(acc);
        return;
    }

    // share the node's 16-vector between its 2 lanes
    float* hr = &hsh[(t >> 1) * 17];
#pragma unroll
    for (int q = 0; q < 8; q++) hr[h * 8 + q] = acc[q];
    __syncwarp();

    if (MODE == 0) {  // 16x16 transform, store pre-scaled by dis
        float o[8];
#pragma unroll
        for (int jj = 0; jj < 8; jj++) {
            int col = h * 8 + jj;
            float s = 0.f;
#pragma unroll
            for (int k = 0; k < 16; k++) s = fmaf(hr[k], wsh[k * 16 + col], s);
            o[jj] = s * di;
        }
        ((uint4*)outF)[row * 2 + h] = f8_to_h8(o);
    } else {  // MODE 2: 16x40 output transform + log_softmax
        float o[20];
#pragma unroll
        for (int jj = 0; jj < 20; jj++) {
            int col = h * 20 + jj;
            float s = bsh[col];
#pragma unroll
            for (int k = 0; k < 16; k++) s = fmaf(hr[k], wsh[k * 40 + col], s);
            o[jj] = s;
        }
        float m = o[0];
#pragma unroll
        for (int jj = 1; jj < 20; jj++) m = fmaxf(m, o[jj]);
        m = fmaxf(m, __shfl_xor_sync(0xffffffffu, m, 1));
        float se = 0.f;
#pragma unroll
        for (int jj = 0; jj < 20; jj++) se += __expf(o[jj] - m);
        se += __shfl_xor_sync(0xffffffffu, se, 1);
        float l = m + __logf(se);
        int node = g_order[row];
#pragma unroll
        for (int jj = 0; jj < 20; jj++)
            fout[(size_t)node * 40 + h * 20 + jj] = o[jj] - l;
    }
}

// ---------------- launch ----------------
extern "C" void kernel_launch(void* const* d_in, const int* in_sizes, int n_in,
                              void* d_out, int out_size) {
    const float* x     = (const float*)d_in[0];
    const float* w_in  = (const float*)d_in[1];
    const float* b_in  = (const float*)d_in[2];
    const float* w_hid = (const float*)d_in[3];
    const float* b_hid = (const float*)d_in[4];
    const float* w_out = (const float*)d_in[5];
    const float* b_out = (const float*)d_in[6];
    const int*   ei    = (const int*)d_in[7];
    float* out = (float*)d_out;

    const int NB_N = (NN + 255) / 256;       // 782
    const int NB_E4 = (EE / 4 + 255) / 256;  // 6250

    // prep: counts -> degree sort -> group bases (+precise pad) -> ELL scatter
    k_zero<<<NB_N, 256>>>();
    k_hist<<<NB_E4, 256>>>(ei);
    k_dhist<<<NB_N, 256>>>();
    k_dplace<<<NB_N, 256>>>();
    k_gmaxscan<<<NGB2, 1024>>>();
    k_sbpad<<<NB_N, 256>>>();
    k_scatter2<<<NB_E4, 256>>>(ei);

    // t0-hat = dis * (x @ w_in)  -> g_hA (rank order)
    k_xw<<<NN / 16, 256>>>(x, w_in);

    // layers 1..8: fused agg + bias + relu + next 16x16 transform (ping-pong)
    k_agg<0><<<NBA, 256>>>(1, b_in,         w_hid + 0 * 256, nullptr, nullptr);
    k_agg<0><<<NBA, 256>>>(0, b_hid + 0*16, w_hid + 1 * 256, nullptr, nullptr);
    k_agg<0><<<NBA, 256>>>(1, b_hid + 1*16, w_hid + 2 * 256, nullptr, nullptr);
    k_agg<0><<<NBA, 256>>>(0, b_hid + 2*16, w_hid + 3 * 256, nullptr, nullptr);
    k_agg<0><<<NBA, 256>>>(1, b_hid + 3*16, w_hid + 4 * 256, nullptr, nullptr);
    k_agg<0><<<NBA, 256>>>(0, b_hid + 4*16, w_hid + 5 * 256, nullptr, nullptr);
    k_agg<0><<<NBA, 256>>>(1, b_hid + 5*16, w_hid + 6 * 256, nullptr, nullptr);
    k_agg<0><<<NBA, 256>>>(0, b_hid + 6*16, w_hid + 7 * 256, nullptr, nullptr);
    // layer 9: h9-hat (hA -> hB)
    k_agg<1><<<NBA, 256>>>(1, b_hid + 7*16, nullptr, nullptr, nullptr);
    // layer 10: out = log_softmax((dis*agg(h9-hat)) @ w_out + b_out)
    k_agg<2><<<NBA, 256>>>(0, nullptr, w_out, b_out, out);
}

// round 14
// speedup vs baseline: 1.1630x; 1.0426x over previous
#include <cuda_runtime.h>
#include <cuda_fp16.h>

#define NN 200000
#define EE 6400000
#define HH 16
#define CC 40
#define NBIN 512
#define ILV 16                      // ELL interleave: 16 nodes per warp-group
#define NG2 (NN / ILV)              // 12500 groups
#define NGB2 ((NG2 + 1023) / 1024)  // 13
#define EIL_CAP 7000000
#define DEPTH 4                     // cp.async pipeline depth
#define NBA 1563                    // agg grid (ceil(NG2/8))
#define BPERM 997                   // block permutation, coprime to 1563=3*521

// ---------------- scratch (static device globals; no allocation) ----------------
__device__ int    g_cnt[NN];
__device__ float  g_dis[NN];        // node order (for k_xw)
__device__ float  g_disP[NN];       // rank order (for k_agg)
__device__ int    g_order[NN];      // rank -> node
__device__ int    g_rank[NN];       // node -> rank
__device__ int2   g_sbc[NN];        // .x cursor (atomic), .y slotbase
__device__ int    g_dbin[NBIN];
__device__ int    g_dcur[NBIN];
__device__ int    g_eil[EIL_CAP];   // x16-interleaved ELL, entries are RANKS
__device__ int    g_gmax[NG2];
__device__ int    g_gscan[NG2];
__device__ int    g_gbsum[NGB2];
__device__ int    g_gbase[NG2 + 1]; // slot base per group (int units)
// features fp16, RANK order, PRE-SCALED by dis; row NN is an always-zero pad row
__device__ __half g_hA[(NN + 1) * HH];
__device__ __half g_hB[(NN + 1) * HH];

// ---------------- prep ----------------
__global__ void k_hist(const int* __restrict__ ei) {  // 4 edges per thread
    int e4 = blockIdx.x * 256 + threadIdx.x;
    if (e4 < EE / 4) {
        int4 d = ((const int4*)(ei + EE))[e4];
        atomicAdd(&g_cnt[d.x], 1);
        atomicAdd(&g_cnt[d.y], 1);
        atomicAdd(&g_cnt[d.z], 1);
        atomicAdd(&g_cnt[d.w], 1);
    }
}

// degree histogram + dis; SMEM-aggregated atomics. Block 0 zeros pad rows.
__global__ void k_dhist() {
    __shared__ int sh[NBIN];
    int t = threadIdx.x;
    sh[t] = 0; sh[t + 256] = 0;
    if (blockIdx.x == 0) {
        if (t < 2) ((uint4*)g_hA)[NN * 2 + t] = make_uint4(0u, 0u, 0u, 0u);
        else if (t < 4) ((uint4*)g_hB)[NN * 2 + (t - 2)] = make_uint4(0u, 0u, 0u, 0u);
    }
    __syncthreads();
    int i = blockIdx.x * 256 + t;
    if (i < NN) {
        int d = g_cnt[i];
        g_dis[i] = rsqrtf((float)(d + 1));
        if (d > NBIN - 1) d = NBIN - 1;
        atomicAdd(&sh[d], 1);
    }
    __syncthreads();
    if (sh[t]) atomicAdd(&g_dbin[t], sh[t]);
    if (sh[t + 256]) atomicAdd(&g_dbin[t + 256], sh[t + 256]);
}

// degree-sorted rank placement; per-block SMEM aggregation
__global__ void k_dplace() {
    __shared__ int pairsc[256];
    __shared__ int doff[NBIN];
    __shared__ int lcnt[NBIN];
    __shared__ int lbase[NBIN];
    int t = threadIdx.x;
    int s0 = g_dbin[2 * t], s1 = g_dbin[2 * t + 1];
    pairsc[t] = s0 + s1;
    lcnt[2 * t] = 0; lcnt[2 * t + 1] = 0;
    for (int off = 1; off < 256; off <<= 1) {
        __syncthreads();
        int u = (t >= off) ? pairsc[t - off] : 0;
        __syncthreads();
        pairsc[t] += u;
    }
    __syncthreads();
    int exp = pairsc[t] - (s0 + s1);   // exclusive pair prefix
    doff[2 * t] = exp;
    doff[2 * t + 1] = exp + s0;
    __syncthreads();

    int i = blockIdx.x * 256 + t;
    int d = -1, lo = 0;
    if (i < NN) {
        d = g_cnt[i]; if (d > NBIN - 1) d = NBIN - 1;
        lo = atomicAdd(&lcnt[d], 1);       // in-block offset (SMEM, fast)
    }
    __syncthreads();
    if (lcnt[2 * t]) lbase[2 * t] = atomicAdd(&g_dcur[2 * t], lcnt[2 * t]);
    if (lcnt[2 * t + 1]) lbase[2 * t + 1] = atomicAdd(&g_dcur[2 * t + 1], lcnt[2 * t + 1]);
    __syncthreads();
    if (i < NN) {
        int p = doff[d] + lbase[d] + lo;
        g_order[p] = i;
        g_rank[i] = p;
        g_disP[p] = g_dis[i];
    }
}

// fused: per-group max degree + 1024-wide inclusive scan of maxes
__global__ void k_gmaxscan() {
    __shared__ int sh[1024];
    int t = threadIdx.x;
    int i = blockIdx.x * 1024 + t;
    int m = 0;
    if (i < NG2) {
#pragma unroll
        for (int j = 0; j < ILV; j++) {
            int d = g_cnt[g_order[i * ILV + j]];
            m = d > m ? d : m;
        }
        g_gmax[i] = m;
    }
    sh[t] = m;
    for (int off = 1; off < 1024; off <<= 1) {
        __syncthreads();
        int u = (t >= off) ? sh[t - off] : 0;
        __syncthreads();
        sh[t] += u;
    }
    __syncthreads();
    if (i < NG2) g_gscan[i] = sh[t];
    if (t == 1023) g_gbsum[blockIdx.x] = sh[1023];
}

// fused: top-level scan + gbase + per-node slotbase + PRECISE ELL padding
__global__ void k_sbpad() {
    __shared__ int boff[NGB2 + 1];
    int t = threadIdx.x;
    if (t == 0) {
        int run = 0;
        for (int j = 0; j < NGB2; j++) { boff[j] = run; run += g_gbsum[j]; }
        boff[NGB2] = run;
    }
    __syncthreads();
    int i = blockIdx.x * 256 + t;
    if (i < NG2) {
        int ex = boff[i >> 10] + g_gscan[i] - g_gmax[i];
        g_gbase[i] = ex * ILV;
    }
    if (i == 0) g_gbase[NG2] = boff[NGB2] * ILV;
    if (i < NN) {
        int r = g_rank[i];
        int g = r >> 4;
        int gm = g_gmax[g];
        int base = (boff[g >> 10] + g_gscan[g] - gm) * ILV;
        int sb = base + (r & 15);
        g_sbc[i].y = sb;
        int deg = g_cnt[i];
        for (int k = deg; k < gm; k++) g_eil[sb + k * ILV] = NN;  // precise pad
    }
}

__global__ void k_scatter2(const int* __restrict__ ei) {  // 4 edges per thread
    int e4 = blockIdx.x * 256 + threadIdx.x;
    if (e4 < EE / 4) {
        int4 s = ((const int4*)ei)[e4];
        int4 d = ((const int4*)(ei + EE))[e4];
#pragma unroll
        for (int q = 0; q < 4; q++) {
            int ss = (q == 0) ? s.x : (q == 1) ? s.y : (q == 2) ? s.z : s.w;
            int dd = (q == 0) ? d.x : (q == 1) ? d.y : (q == 2) ? d.z : d.w;
            int i = atomicAdd(&g_sbc[dd].x, 1);
            int sb = g_sbc[dd].y;
            g_eil[sb + i * ILV] = g_rank[ss];
        }
    }
}

// -------- first transform: g_hA[rank(n)] = dis[n] * (x[n] @ w_in) --------
__global__ __launch_bounds__(256) void k_xw(const float* __restrict__ x,
                                            const float* __restrict__ w) {
    __shared__ float xs[16 * 128];
    __shared__ float ws[128 * 16];
    int t = threadIdx.x;
    for (int i = t; i < 512; i += 256) ((float4*)ws)[i] = ((const float4*)w)[i];
    const float4* xb = (const float4*)(x + (size_t)blockIdx.x * 2048);
    for (int i = t; i < 512; i += 256) ((float4*)xs)[i] = xb[i];
    __syncthreads();
    int ry = t >> 4, c = t & 15;
    float s = 0.f;
#pragma unroll
    for (int k = 0; k < 128; k++) s = fmaf(xs[ry * 128 + k], ws[k * 16 + c], s);
    int node = blockIdx.x * 16 + ry;
    g_hA[(size_t)g_rank[node] * 16 + c] = __float2half_rn(s * g_dis[node]);
}

// ---------------- cp.async helpers ----------------
__device__ __forceinline__ void cp16(unsigned smem, const void* gptr) {
    asm volatile("cp.async.cg.shared.global [%0], [%1], 16;"
                 :: "r"(smem), "l"(gptr) : "memory");
}
__device__ __forceinline__ void cp_commit() {
    asm volatile("cp.async.commit_group;" ::: "memory");
}
template <int N>
__device__ __forceinline__ void cp_wait() {
    asm volatile("cp.async.wait_group %0;" :: "n"(N) : "memory");
}

__device__ __forceinline__ void h8_init(float* a, uint4 v) {
    __half2* h = (__half2*)&v;
#pragma unroll
    for (int q = 0; q < 4; q++) {
        float2 f = __half22float2(h[q]);
        a[2 * q] = f.x; a[2 * q + 1] = f.y;
    }
}
__device__ __forceinline__ void h8_add(float* a, uint4 v) {
    __half2* h = (__half2*)&v;
#pragma unroll
    for (int q = 0; q < 4; q++) {
        float2 f = __half22float2(h[q]);
        a[2 * q] += f.x; a[2 * q + 1] += f.y;
    }
}
__device__ __forceinline__ uint4 f8_to_h8(const float* a) {
    uint4 r;
    __half2* h = (__half2*)&r;
#pragma unroll
    for (int q = 0; q < 4; q++) h[q] = __floats2half2_rn(a[2 * q], a[2 * q + 1]);
    return r;
}

// ---------------- fused aggregation layers (cp.async gather pipeline) -------
// MODE 0: h = relu(dis*agg+b); store dis*(h @ Wn)    [8x]
// MODE 1: store dis*relu(dis*agg+b)                   [h9]
// MODE 2: o = (dis*agg) @ w_out + b_out; log_softmax  [final]
template <int MODE>
__global__ __launch_bounds__(256) void k_agg(int inA,
                                             const float* __restrict__ preBias,
                                             const float* __restrict__ Wn,
                                             const float* __restrict__ postBias,
                                             float* __restrict__ fout) {
    __shared__ uint4 stage[8][DEPTH][32];
    __shared__ float wsh[640];
    __shared__ float bsh[40];
    __shared__ float hsh[128 * 17];
    int t = threadIdx.x;
    if (MODE == 0) wsh[t] = Wn[t & 255];
    if (MODE == 2) {
        for (int i = t; i < 640; i += 256) wsh[i] = Wn[i];
        if (t < 40) bsh[t] = postBias[t];
    }
    __syncthreads();

    int w = t >> 5, lane = t & 31;
    // block-level degree swizzle: spreads degree-sorted work across SMs/waves
    int b = (int)(((long long)blockIdx.x * BPERM) % NBA);
    int gw = b * 8 + w;
    if (gw >= NG2) return;

    const uint4* tab = (const uint4*)(inA ? g_hA : g_hB);
    __half* outF = inA ? g_hB : g_hA;

    int j = lane >> 1, h = lane & 1;
    int row = gw * ILV + j;            // rank-ordered feature row
    float di = g_disP[row];

    float acc[8];
    h8_init(acc, __ldg(&tab[row * 2 + h]));   // self loop (coalesced)

    int base = g_gbase[gw];
    int nch = (g_gbase[gw + 1] - base) >> 4;
    const int* eilc = g_eil + base + j;
    unsigned sa0 = (unsigned)__cvta_generic_to_shared(&stage[w][0][lane]);

    int npro = nch < DEPTH ? nch : DEPTH;
    for (int c = 0; c < npro; c++) {
        int src = __ldg(eilc + c * ILV);
        cp16(sa0 + (c & (DEPTH - 1)) * 512, tab + src * 2 + h);
        cp_commit();
    }
    int c = 0;
    // steady state: consume 2 chunks per wait, issue 2
    for (; c + DEPTH + 1 < nch; c += 2) {
        cp_wait<DEPTH - 2>();                       // chunks c, c+1 ready
        h8_add(acc, stage[w][c & (DEPTH - 1)][lane]);
        h8_add(acc, stage[w][(c + 1) & (DEPTH - 1)][lane]);
        int c0 = c + DEPTH, c1 = c + DEPTH + 1;
        int s0 = __ldg(eilc + c0 * ILV);
        int s1 = __ldg(eilc + c1 * ILV);
        cp16(sa0 + (c0 & (DEPTH - 1)) * 512, tab + s0 * 2 + h);
        cp_commit();
        cp16(sa0 + (c1 & (DEPTH - 1)) * 512, tab + s1 * 2 + h);
        cp_commit();
    }
    cp_wait<0>();
    for (; c < nch; c++) h8_add(acc, stage[w][c & (DEPTH - 1)][lane]);

#pragma unroll
    for (int q = 0; q < 8; q++) acc[q] *= di;

    if (MODE != 2) {  // bias + relu
        const float* bp = preBias + h * 8;
#pragma unroll
        for (int q = 0; q < 8; q++) acc[q] = fmaxf(acc[q] + __ldg(bp + q), 0.f);
    }

    if (MODE == 1) {  // store dis*h (coalesced, rank order)
#pragma unroll
        for (int q = 0; q < 8; q++) acc[q] *= di;
        ((uint4*)outF)[row * 2 + h] = f8_to_h8(acc);
        return;
    }

    // share the node's 16-vector between its 2 lanes
    float* hr = &hsh[(t >> 1) * 17];
#pragma unroll
    for (int q = 0; q < 8; q++) hr[h * 8 + q] = acc[q];
    __syncwarp();

    if (MODE == 0) {  // 16x16 transform, store pre-scaled by dis
        float o[8];
#pragma unroll
        for (int jj = 0; jj < 8; jj++) {
            int col = h * 8 + jj;
            float s = 0.f;
#pragma unroll
            for (int k = 0; k < 16; k++) s = fmaf(hr[k], wsh[k * 16 + col], s);
            o[jj] = s * di;
        }
        ((uint4*)outF)[row * 2 + h] = f8_to_h8(o);
    } else {  // MODE 2: 16x40 output transform + log_softmax
        float o[20];
#pragma unroll
        for (int jj = 0; jj < 20; jj++) {
            int col = h * 20 + jj;
            float s = bsh[col];
#pragma unroll
            for (int k = 0; k < 16; k++) s = fmaf(hr[k], wsh[k * 40 + col], s);
            o[jj] = s;
        }
        float m = o[0];
#pragma unroll
        for (int jj = 1; jj < 20; jj++) m = fmaxf(m, o[jj]);
        m = fmaxf(m, __shfl_xor_sync(0xffffffffu, m, 1));
        float se = 0.f;
#pragma unroll
        for (int jj = 0; jj < 20; jj++) se += __expf(o[jj] - m);
        se += __shfl_xor_sync(0xffffffffu, se, 1);
        float l = m + __logf(se);
        int node = g_order[row];
#pragma unroll
        for (int jj = 0; jj < 20; jj++)
            fout[(size_t)node * 40 + h * 20 + jj] = o[jj] - l;
    }
}

// ---------------- launch ----------------
extern "C" void kernel_launch(void* const* d_in, const int* in_sizes, int n_in,
                              void* d_out, int out_size) {
    const float* x     = (const float*)d_in[0];
    const float* w_in  = (const float*)d_in[1];
    const float* b_in  = (const float*)d_in[2];
    const float* w_hid = (const float*)d_in[3];
    const float* b_hid = (const float*)d_in[4];
    const float* w_out = (const float*)d_in[5];
    const float* b_out = (const float*)d_in[6];
    const int*   ei    = (const int*)d_in[7];
    float* out = (float*)d_out;

    const int NB_N = (NN + 255) / 256;       // 782
    const int NB_E4 = (EE / 4 + 255) / 256;  // 6250

    // zero scratch via DMA memsets (replaces the k_zero kernel)
    void *p_cnt, *p_sbc, *p_dbin, *p_dcur;
    cudaGetSymbolAddress(&p_cnt, g_cnt);
    cudaGetSymbolAddress(&p_sbc, g_sbc);
    cudaGetSymbolAddress(&p_dbin, g_dbin);
    cudaGetSymbolAddress(&p_dcur, g_dcur);
    cudaMemsetAsync(p_cnt, 0, NN * sizeof(int));
    cudaMemsetAsync(p_sbc, 0, NN * sizeof(int2));
    cudaMemsetAsync(p_dbin, 0, NBIN * sizeof(int));
    cudaMemsetAsync(p_dcur, 0, NBIN * sizeof(int));

    // prep: counts -> degree sort -> group bases (+precise pad) -> ELL scatter
    k_hist<<<NB_E4, 256>>>(ei);
    k_dhist<<<NB_N, 256>>>();
    k_dplace<<<NB_N, 256>>>();
    k_gmaxscan<<<NGB2, 1024>>>();
    k_sbpad<<<NB_N, 256>>>();
    k_scatter2<<<NB_E4, 256>>>(ei);

    // t0-hat = dis * (x @ w_in)  -> g_hA (rank order)
    k_xw<<<NN / 16, 256>>>(x, w_in);

    // layers 1..8: fused agg + bias + relu + next 16x16 transform (ping-pong)
    k_agg<0><<<NBA, 256>>>(1, b_in,         w_hid + 0 * 256, nullptr, nullptr);
    k_agg<0><<<NBA, 256>>>(0, b_hid + 0*16, w_hid + 1 * 256, nullptr, nullptr);
    k_agg<0><<<NBA, 256>>>(1, b_hid + 1*16, w_hid + 2 * 256, nullptr, nullptr);
    k_agg<0><<<NBA, 256>>>(0, b_hid + 2*16, w_hid + 3 * 256, nullptr, nullptr);
    k_agg<0><<<NBA, 256>>>(1, b_hid + 3*16, w_hid + 4 * 256, nullptr, nullptr);
    k_agg<0><<<NBA, 256>>>(0, b_hid + 4*16, w_hid + 5 * 256, nullptr, nullptr);
    k_agg<0><<<NBA, 256>>>(1, b_hid + 5*16, w_hid + 6 * 256, nullptr, nullptr);
    k_agg<0><<<NBA, 256>>>(0, b_hid + 6*16, w_hid + 7 * 256, nullptr, nullptr);
    // layer 9: h9-hat (hA -> hB)
    k_agg<1><<<NBA, 256>>>(1, b_hid + 7*16, nullptr, nullptr, nullptr);
    // layer 10: out = log_softmax((dis*agg(h9-hat)) @ w_out + b_out)
    k_agg<2><<<NBA, 256>>>(0, nullptr, w_out, b_out, out);
}

// round 15
// speedup vs baseline: 1.1835x; 1.0176x over previous
#include <cuda_runtime.h>
#include <cuda_fp16.h>

#define NN 200000
#define EE 6400000
#define HH 16
#define CC 40
#define NBIN 512
#define ILV 16                      // ELL interleave: 16 nodes per warp-group
#define NG2 (NN / ILV)              // 12500 groups
#define NGB2 ((NG2 + 1023) / 1024)  // 13
#define EIL_CAP 7000000
#define DEPTH 4                     // cp.async pipeline depth
#define NBA 1563                    // agg grid (ceil(NG2/8))
#define BPERM 997                   // block permutation, coprime to 1563=3*521

// ---------------- scratch (static device globals; no allocation) ----------------
__device__ int    g_cnt[NN];
__device__ float  g_dis[NN];        // node order (for k_xw)
__device__ float  g_disP[NN];       // rank order (for k_agg)
__device__ int    g_degP[NN];       // rank-ordered degree (ascending)
__device__ int    g_order[NN];      // rank -> node
__device__ int    g_rank[NN];       // node -> rank
__device__ int2   g_sbc[NN];        // .x cursor (atomic), .y slotbase
__device__ int    g_dbin[NBIN];
__device__ int    g_dcur[NBIN];
__device__ int    g_eil[EIL_CAP];   // x16-interleaved ELL, entries are RANKS
__device__ int    g_gmax[NG2];
__device__ int    g_gscan[NG2];
__device__ int    g_gbsum[NGB2];
__device__ int    g_gbase[NG2 + 1]; // slot base per group (int units)
// features fp16, RANK order, PRE-SCALED by dis; row NN is an always-zero pad row
__device__ __half g_hA[(NN + 1) * HH];
__device__ __half g_hB[(NN + 1) * HH];

// ---------------- prep ----------------
__global__ void k_hist(const int* __restrict__ ei) {  // 4 edges per thread
    int e4 = blockIdx.x * 256 + threadIdx.x;
    if (e4 < EE / 4) {
        int4 d = ((const int4*)(ei + EE))[e4];
        atomicAdd(&g_cnt[d.x], 1);
        atomicAdd(&g_cnt[d.y], 1);
        atomicAdd(&g_cnt[d.z], 1);
        atomicAdd(&g_cnt[d.w], 1);
    }
}

// degree histogram + dis; SMEM-aggregated atomics. Block 0 zeros pad rows.
__global__ void k_dhist() {
    __shared__ int sh[NBIN];
    int t = threadIdx.x;
    sh[t] = 0; sh[t + 256] = 0;
    if (blockIdx.x == 0) {
        if (t < 2) ((uint4*)g_hA)[NN * 2 + t] = make_uint4(0u, 0u, 0u, 0u);
        else if (t < 4) ((uint4*)g_hB)[NN * 2 + (t - 2)] = make_uint4(0u, 0u, 0u, 0u);
    }
    __syncthreads();
    int i = blockIdx.x * 256 + t;
    if (i < NN) {
        int d = g_cnt[i];
        g_dis[i] = rsqrtf((float)(d + 1));
        if (d > NBIN - 1) d = NBIN - 1;
        atomicAdd(&sh[d], 1);
    }
    __syncthreads();
    if (sh[t]) atomicAdd(&g_dbin[t], sh[t]);
    if (sh[t + 256]) atomicAdd(&g_dbin[t + 256], sh[t + 256]);
}

// degree-sorted rank placement; per-block SMEM aggregation
__global__ void k_dplace() {
    __shared__ int pairsc[256];
    __shared__ int doff[NBIN];
    __shared__ int lcnt[NBIN];
    __shared__ int lbase[NBIN];
    int t = threadIdx.x;
    int s0 = g_dbin[2 * t], s1 = g_dbin[2 * t + 1];
    pairsc[t] = s0 + s1;
    lcnt[2 * t] = 0; lcnt[2 * t + 1] = 0;
    for (int off = 1; off < 256; off <<= 1) {
        __syncthreads();
        int u = (t >= off) ? pairsc[t - off] : 0;
        __syncthreads();
        pairsc[t] += u;
    }
    __syncthreads();
    int exp = pairsc[t] - (s0 + s1);   // exclusive pair prefix
    doff[2 * t] = exp;
    doff[2 * t + 1] = exp + s0;
    __syncthreads();

    int i = blockIdx.x * 256 + t;
    int d = -1, lo = 0, dfull = 0;
    if (i < NN) {
        dfull = g_cnt[i];
        d = dfull; if (d > NBIN - 1) d = NBIN - 1;
        lo = atomicAdd(&lcnt[d], 1);       // in-block offset (SMEM, fast)
    }
    __syncthreads();
    if (lcnt[2 * t]) lbase[2 * t] = atomicAdd(&g_dcur[2 * t], lcnt[2 * t]);
    if (lcnt[2 * t + 1]) lbase[2 * t + 1] = atomicAdd(&g_dcur[2 * t + 1], lcnt[2 * t + 1]);
    __syncthreads();
    if (i < NN) {
        int p = doff[d] + lbase[d] + lo;
        g_order[p] = i;
        g_rank[i] = p;
        g_disP[p] = g_dis[i];
        g_degP[p] = dfull;                 // rank-ordered degree
    }
}

// fused: per-group max degree + 1024-wide inclusive scan of maxes.
// Ranks are degree-sorted ascending, so group max = degree of last rank in
// group (exact-max fallback only if the group reaches the clamped top bin).
__global__ void k_gmaxscan() {
    __shared__ int sh[1024];
    int t = threadIdx.x;
    int i = blockIdx.x * 1024 + t;
    int m = 0;
    if (i < NG2) {
        m = g_degP[i * ILV + ILV - 1];
        if (m >= NBIN - 1) {               // top-bin order is arbitrary: exact max
            m = 0;
#pragma unroll
            for (int j = 0; j < ILV; j++) {
                int d = g_degP[i * ILV + j];
                m = d > m ? d : m;
            }
        }
        g_gmax[i] = m;
    }
    sh[t] = m;
    for (int off = 1; off < 1024; off <<= 1) {
        __syncthreads();
        int u = (t >= off) ? sh[t - off] : 0;
        __syncthreads();
        sh[t] += u;
    }
    __syncthreads();
    if (i < NG2) g_gscan[i] = sh[t];
    if (t == 1023) g_gbsum[blockIdx.x] = sh[1023];
}

// fused: top-level scan + gbase + per-node slotbase + PRECISE ELL padding
__global__ void k_sbpad() {
    __shared__ int boff[NGB2 + 1];
    int t = threadIdx.x;
    if (t == 0) {
        int run = 0;
        for (int j = 0; j < NGB2; j++) { boff[j] = run; run += g_gbsum[j]; }
        boff[NGB2] = run;
    }
    __syncthreads();
    int i = blockIdx.x * 256 + t;
    if (i < NG2) {
        int ex = boff[i >> 10] + g_gscan[i] - g_gmax[i];
        g_gbase[i] = ex * ILV;
    }
    if (i == 0) g_gbase[NG2] = boff[NGB2] * ILV;
    if (i < NN) {
        int r = g_rank[i];
        int g = r >> 4;
        int gm = g_gmax[g];
        int base = (boff[g >> 10] + g_gscan[g] - gm) * ILV;
        int sb = base + (r & 15);
        g_sbc[i].y = sb;
        int deg = g_cnt[i];
        for (int k = deg; k < gm; k++) g_eil[sb + k * ILV] = NN;  // precise pad
    }
}

__global__ void k_scatter2(const int* __restrict__ ei) {  // 4 edges per thread
    int e4 = blockIdx.x * 256 + threadIdx.x;
    if (e4 < EE / 4) {
        int4 s = ((const int4*)ei)[e4];
        int4 d = ((const int4*)(ei + EE))[e4];
#pragma unroll
        for (int q = 0; q < 4; q++) {
            int ss = (q == 0) ? s.x : (q == 1) ? s.y : (q == 2) ? s.z : s.w;
            int dd = (q == 0) ? d.x : (q == 1) ? d.y : (q == 2) ? d.z : d.w;
            int i = atomicAdd(&g_sbc[dd].x, 1);
            int sb = g_sbc[dd].y;
            g_eil[sb + i * ILV] = g_rank[ss];
        }
    }
}

// -------- first transform: g_hA[rank(n)] = dis[n] * (x[n] @ w_in) --------
__global__ __launch_bounds__(256) void k_xw(const float* __restrict__ x,
                                            const float* __restrict__ w) {
    __shared__ float xs[16 * 128];
    __shared__ float ws[128 * 16];
    int t = threadIdx.x;
    for (int i = t; i < 512; i += 256) ((float4*)ws)[i] = ((const float4*)w)[i];
    const float4* xb = (const float4*)(x + (size_t)blockIdx.x * 2048);
    for (int i = t; i < 512; i += 256) ((float4*)xs)[i] = xb[i];
    __syncthreads();
    int ry = t >> 4, c = t & 15;
    float s = 0.f;
#pragma unroll
    for (int k = 0; k < 128; k++) s = fmaf(xs[ry * 128 + k], ws[k * 16 + c], s);
    int node = blockIdx.x * 16 + ry;
    g_hA[(size_t)g_rank[node] * 16 + c] = __float2half_rn(s * g_dis[node]);
}

// ---------------- cp.async helpers ----------------
__device__ __forceinline__ void cp16(unsigned smem, const void* gptr) {
    asm volatile("cp.async.cg.shared.global [%0], [%1], 16;"
                 :: "r"(smem), "l"(gptr) : "memory");
}
__device__ __forceinline__ void cp_commit() {
    asm volatile("cp.async.commit_group;" ::: "memory");
}
template <int N>
__device__ __forceinline__ void cp_wait() {
    asm volatile("cp.async.wait_group %0;" :: "n"(N) : "memory");
}

__device__ __forceinline__ void h8_init(float* a, uint4 v) {
    __half2* h = (__half2*)&v;
#pragma unroll
    for (int q = 0; q < 4; q++) {
        float2 f = __half22float2(h[q]);
        a[2 * q] = f.x; a[2 * q + 1] = f.y;
    }
}
__device__ __forceinline__ void h8_add(float* a, uint4 v) {
    __half2* h = (__half2*)&v;
#pragma unroll
    for (int q = 0; q < 4; q++) {
        float2 f = __half22float2(h[q]);
        a[2 * q] += f.x; a[2 * q + 1] += f.y;
    }
}
__device__ __forceinline__ uint4 f8_to_h8(const float* a) {
    uint4 r;
    __half2* h = (__half2*)&r;
#pragma unroll
    for (int q = 0; q < 4; q++) h[q] = __floats2half2_rn(a[2 * q], a[2 * q + 1]);
    return r;
}

// ---------------- fused aggregation layers (cp.async gather pipeline) -------
// MODE 0: h = relu(dis*agg+b); store dis*(h @ Wn)    [8x]
// MODE 1: store dis*relu(dis*agg+b)                   [h9]
// MODE 2: o = (dis*agg) @ w_out + b_out; log_softmax  [final]
template <int MODE>
__global__ __launch_bounds__(256) void k_agg(int inA,
                                             const float* __restrict__ preBias,
                                             const float* __restrict__ Wn,
                                             const float* __restrict__ postBias,
                                             float* __restrict__ fout) {
    __shared__ uint4 stage[8][DEPTH][32];
    __shared__ float wsh[640];
    __shared__ float bsh[40];
    __shared__ float hsh[128 * 17];
    int t = threadIdx.x;
    if (MODE == 0) wsh[t] = Wn[t & 255];
    if (MODE == 2) {
        for (int i = t; i < 640; i += 256) wsh[i] = Wn[i];
        if (t < 40) bsh[t] = postBias[t];
    }
    __syncthreads();

    int w = t >> 5, lane = t & 31;
    // block-level degree swizzle: spreads degree-sorted work across SMs/waves
    int b = (int)(((long long)blockIdx.x * BPERM) % NBA);
    int gw = b * 8 + w;
    if (gw >= NG2) return;

    const uint4* tab = (const uint4*)(inA ? g_hA : g_hB);
    __half* outF = inA ? g_hB : g_hA;

    int j = lane >> 1, h = lane & 1;
    int row = gw * ILV + j;            // rank-ordered feature row
    float di = g_disP[row];

    float acc[8];
    h8_init(acc, __ldg(&tab[row * 2 + h]));   // self loop (coalesced)

    int base = g_gbase[gw];
    int nch = (g_gbase[gw + 1] - base) >> 4;
    const int* eilc = g_eil + base + j;
    unsigned sa0 = (unsigned)__cvta_generic_to_shared(&stage[w][0][lane]);

    int npro = nch < DEPTH ? nch : DEPTH;
    for (int c = 0; c < npro; c++) {
        int src = __ldg(eilc + c * ILV);
        cp16(sa0 + (c & (DEPTH - 1)) * 512, tab + src * 2 + h);
        cp_commit();
    }
    int c = 0;
    // steady state: consume 2 chunks per wait, issue 2
    for (; c + DEPTH + 1 < nch; c += 2) {
        cp_wait<DEPTH - 2>();                       // chunks c, c+1 ready
        h8_add(acc, stage[w][c & (DEPTH - 1)][lane]);
        h8_add(acc, stage[w][(c + 1) & (DEPTH - 1)][lane]);
        int c0 = c + DEPTH, c1 = c + DEPTH + 1;
        int s0 = __ldg(eilc + c0 * ILV);
        int s1 = __ldg(eilc + c1 * ILV);
        cp16(sa0 + (c0 & (DEPTH - 1)) * 512, tab + s0 * 2 + h);
        cp_commit();
        cp16(sa0 + (c1 & (DEPTH - 1)) * 512, tab + s1 * 2 + h);
        cp_commit();
    }
    cp_wait<0>();
    for (; c < nch; c++) h8_add(acc, stage[w][c & (DEPTH - 1)][lane]);

#pragma unroll
    for (int q = 0; q < 8; q++) acc[q] *= di;

    if (MODE != 2) {  // bias + relu
        const float* bp = preBias + h * 8;
#pragma unroll
        for (int q = 0; q < 8; q++) acc[q] = fmaxf(acc[q] + __ldg(bp + q), 0.f);
    }

    if (MODE == 1) {  // store dis*h (coalesced, rank order)
#pragma unroll
        for (int q = 0; q < 8; q++) acc[q] *= di;
        ((uint4*)outF)[row * 2 + h] = f8_to_h8(acc);
        return;
    }

    // share the node's 16-vector between its 2 lanes
    float* hr = &hsh[(t >> 1) * 17];
#pragma unroll
    for (int q = 0; q < 8; q++) hr[h * 8 + q] = acc[q];
    __syncwarp();

    if (MODE == 0) {  // 16x16 transform, store pre-scaled by dis
        float o[8];
#pragma unroll
        for (int jj = 0; jj < 8; jj++) {
            int col = h * 8 + jj;
            float s = 0.f;
#pragma unroll
            for (int k = 0; k < 16; k++) s = fmaf(hr[k], wsh[k * 16 + col], s);
            o[jj] = s * di;
        }
        ((uint4*)outF)[row * 2 + h] = f8_to_h8(o);
    } else {  // MODE 2: 16x40 output transform + log_softmax
        float o[20];
#pragma unroll
        for (int jj = 0; jj < 20; jj++) {
            int col = h * 20 + jj;
            float s = bsh[col];
#pragma unroll
            for (int k = 0; k < 16; k++) s = fmaf(hr[k], wsh[k * 40 + col], s);
            o[jj] = s;
        }
        float m = o[0];
#pragma unroll
        for (int jj = 1; jj < 20; jj++) m = fmaxf(m, o[jj]);
        m = fmaxf(m, __shfl_xor_sync(0xffffffffu, m, 1));
        float se = 0.f;
#pragma unroll
        for (int jj = 0; jj < 20; jj++) se += __expf(o[jj] - m);
        se += __shfl_xor_sync(0xffffffffu, se, 1);
        float l = m + __logf(se);
        int node = g_order[row];
#pragma unroll
        for (int jj = 0; jj < 20; jj++)
            fout[(size_t)node * 40 + h * 20 + jj] = o[jj] - l;
    }
}

// ---------------- launch ----------------
extern "C" void kernel_launch(void* const* d_in, const int* in_sizes, int n_in,
                              void* d_out, int out_size) {
    const float* x     = (const float*)d_in[0];
    const float* w_in  = (const float*)d_in[1];
    const float* b_in  = (const float*)d_in[2];
    const float* w_hid = (const float*)d_in[3];
    const float* b_hid = (const float*)d_in[4];
    const float* w_out = (const float*)d_in[5];
    const float* b_out = (const float*)d_in[6];
    const int*   ei    = (const int*)d_in[7];
    float* out = (float*)d_out;

    const int NB_N = (NN + 255) / 256;       // 782
    const int NB_E4 = (EE / 4 + 255) / 256;  // 6250

    // zero scratch via DMA memsets (replaces the k_zero kernel)
    void *p_cnt, *p_sbc, *p_dbin, *p_dcur;
    cudaGetSymbolAddress(&p_cnt, g_cnt);
    cudaGetSymbolAddress(&p_sbc, g_sbc);
    cudaGetSymbolAddress(&p_dbin, g_dbin);
    cudaGetSymbolAddress(&p_dcur, g_dcur);
    cudaMemsetAsync(p_cnt, 0, NN * sizeof(int));
    cudaMemsetAsync(p_sbc, 0, NN * sizeof(int2));
    cudaMemsetAsync(p_dbin, 0, NBIN * sizeof(int));
    cudaMemsetAsync(p_dcur, 0, NBIN * sizeof(int));

    // prep: counts -> degree sort -> group bases (+precise pad) -> ELL scatter
    k_hist<<<NB_E4, 256>>>(ei);
    k_dhist<<<NB_N, 256>>>();
    k_dplace<<<NB_N, 256>>>();
    k_gmaxscan<<<NGB2, 1024>>>();
    k_sbpad<<<NB_N, 256>>>();
    k_scatter2<<<NB_E4, 256>>>(ei);

    // t0-hat = dis * (x @ w_in)  -> g_hA (rank order)
    k_xw<<<NN / 16, 256>>>(x, w_in);

    // layers 1..8: fused agg + bias + relu + next 16x16 transform (ping-pong)
    k_agg<0><<<NBA, 256>>>(1, b_in,         w_hid + 0 * 256, nullptr, nullptr);
    k_agg<0><<<NBA, 256>>>(0, b_hid + 0*16, w_hid + 1 * 256, nullptr, nullptr);
    k_agg<0><<<NBA, 256>>>(1, b_hid + 1*16, w_hid + 2 * 256, nullptr, nullptr);
    k_agg<0><<<NBA, 256>>>(0, b_hid + 2*16, w_hid + 3 * 256, nullptr, nullptr);
    k_agg<0><<<NBA, 256>>>(1, b_hid + 3*16, w_hid + 4 * 256, nullptr, nullptr);
    k_agg<0><<<NBA, 256>>>(0, b_hid + 4*16, w_hid + 5 * 256, nullptr, nullptr);
    k_agg<0><<<NBA, 256>>>(1, b_hid + 5*16, w_hid + 6 * 256, nullptr, nullptr);
    k_agg<0><<<NBA, 256>>>(0, b_hid + 6*16, w_hid + 7 * 256, nullptr, nullptr);
    // layer 9: h9-hat (hA -> hB)
    k_agg<1><<<NBA, 256>>>(1, b_hid + 7*16, nullptr, nullptr, nullptr);
    // layer 10: out = log_softmax((dis*agg(h9-hat)) @ w_out + b_out)
    k_agg<2><<<NBA, 256>>>(0, nullptr, w_out, b_out, out);
}

// round 16
// speedup vs baseline: 1.1848x; 1.0011x over previous
#include <cuda_runtime.h>
#include <cuda_fp16.h>

#define NN 200000
#define EE 6400000
#define HH 16
#define CC 40
#define NBIN 512
#define ILV 16                      // ELL interleave: 16 nodes per warp-group
#define NG2 (NN / ILV)              // 12500 groups
#define NGB2 ((NG2 + 1023) / 1024)  // 13
#define EIL_CAP 7000000
#define DEPTH 4                     // cp.async pipeline depth
#define NBA 1563                    // agg grid (ceil(NG2/8))
#define BPERM 997                   // block permutation, coprime to 1563=3*521

// ---------------- scratch (static device globals; no allocation) ----------------
__device__ int    g_cnt[NN];
__device__ float  g_dis[NN];        // node order (for k_xw)
__device__ float  g_disP[NN];       // rank order (for k_agg)
__device__ int    g_degP[NN];       // rank-ordered degree (ascending)
__device__ int    g_order[NN];      // rank -> node
__device__ int    g_rank[NN];       // node -> rank
__device__ int2   g_sbc[NN];        // .x cursor (atomic), .y slotbase
__device__ int    g_dbin[NBIN];
__device__ int    g_dcur[NBIN];
__device__ int    g_eil[EIL_CAP];   // x16-interleaved ELL, entries are RANKS
__device__ int    g_gmax[NG2];
__device__ int    g_gscan[NG2];
__device__ int    g_gbsum[NGB2];
__device__ int    g_gbase[NG2 + 1]; // slot base per group (int units)
// features fp16, RANK order, PRE-SCALED by dis; row NN is an always-zero pad row
__device__ __half g_hA[(NN + 1) * HH];
__device__ __half g_hB[(NN + 1) * HH];

// ---------------- prep ----------------
__global__ void k_hist(const int* __restrict__ ei) {  // 4 edges per thread
    int e4 = blockIdx.x * 256 + threadIdx.x;
    if (e4 < EE / 4) {
        int4 d = ((const int4*)(ei + EE))[e4];
        atomicAdd(&g_cnt[d.x], 1);
        atomicAdd(&g_cnt[d.y], 1);
        atomicAdd(&g_cnt[d.z], 1);
        atomicAdd(&g_cnt[d.w], 1);
    }
}

// degree histogram + dis; SMEM-aggregated atomics. Block 0 zeros pad rows.
__global__ void k_dhist() {
    __shared__ int sh[NBIN];
    int t = threadIdx.x;
    sh[t] = 0; sh[t + 256] = 0;
    if (blockIdx.x == 0) {
        if (t < 2) ((uint4*)g_hA)[NN * 2 + t] = make_uint4(0u, 0u, 0u, 0u);
        else if (t < 4) ((uint4*)g_hB)[NN * 2 + (t - 2)] = make_uint4(0u, 0u, 0u, 0u);
    }
    __syncthreads();
    int i = blockIdx.x * 256 + t;
    if (i < NN) {
        int d = g_cnt[i];
        g_dis[i] = rsqrtf((float)(d + 1));
        if (d > NBIN - 1) d = NBIN - 1;
        atomicAdd(&sh[d], 1);
    }
    __syncthreads();
    if (sh[t]) atomicAdd(&g_dbin[t], sh[t]);
    if (sh[t + 256]) atomicAdd(&g_dbin[t + 256], sh[t + 256]);
}

// degree-sorted rank placement; per-block SMEM aggregation
__global__ void k_dplace() {
    __shared__ int pairsc[256];
    __shared__ int doff[NBIN];
    __shared__ int lcnt[NBIN];
    __shared__ int lbase[NBIN];
    int t = threadIdx.x;
    int s0 = g_dbin[2 * t], s1 = g_dbin[2 * t + 1];
    pairsc[t] = s0 + s1;
    lcnt[2 * t] = 0; lcnt[2 * t + 1] = 0;
    for (int off = 1; off < 256; off <<= 1) {
        __syncthreads();
        int u = (t >= off) ? pairsc[t - off] : 0;
        __syncthreads();
        pairsc[t] += u;
    }
    __syncthreads();
    int exp = pairsc[t] - (s0 + s1);   // exclusive pair prefix
    doff[2 * t] = exp;
    doff[2 * t + 1] = exp + s0;
    __syncthreads();

    int i = blockIdx.x * 256 + t;
    int d = -1, lo = 0, dfull = 0;
    if (i < NN) {
        dfull = g_cnt[i];
        d = dfull; if (d > NBIN - 1) d = NBIN - 1;
        lo = atomicAdd(&lcnt[d], 1);       // in-block offset (SMEM, fast)
    }
    __syncthreads();
    if (lcnt[2 * t]) lbase[2 * t] = atomicAdd(&g_dcur[2 * t], lcnt[2 * t]);
    if (lcnt[2 * t + 1]) lbase[2 * t + 1] = atomicAdd(&g_dcur[2 * t + 1], lcnt[2 * t + 1]);
    __syncthreads();
    if (i < NN) {
        int p = doff[d] + lbase[d] + lo;
        g_order[p] = i;
        g_rank[i] = p;
        g_disP[p] = g_dis[i];
        g_degP[p] = dfull;                 // rank-ordered degree
    }
}

// fused: per-group max degree + 1024-wide inclusive scan of maxes.
// Ranks are degree-sorted ascending, so group max = degree of last rank in
// group (exact-max fallback only if the group reaches the clamped top bin).
__global__ void k_gmaxscan() {
    __shared__ int sh[1024];
    int t = threadIdx.x;
    int i = blockIdx.x * 1024 + t;
    int m = 0;
    if (i < NG2) {
        m = g_degP[i * ILV + ILV - 1];
        if (m >= NBIN - 1) {               // top-bin order is arbitrary: exact max
            m = 0;
#pragma unroll
            for (int j = 0; j < ILV; j++) {
                int d = g_degP[i * ILV + j];
                m = d > m ? d : m;
            }
        }
        g_gmax[i] = m;
    }
    sh[t] = m;
    for (int off = 1; off < 1024; off <<= 1) {
        __syncthreads();
        int u = (t >= off) ? sh[t - off] : 0;
        __syncthreads();
        sh[t] += u;
    }
    __syncthreads();
    if (i < NG2) g_gscan[i] = sh[t];
    if (t == 1023) g_gbsum[blockIdx.x] = sh[1023];
}

// fused: top-level scan + gbase + per-node slotbase + PRECISE ELL padding
__global__ void k_sbpad() {
    __shared__ int boff[NGB2 + 1];
    int t = threadIdx.x;
    if (t == 0) {
        int run = 0;
        for (int j = 0; j < NGB2; j++) { boff[j] = run; run += g_gbsum[j]; }
        boff[NGB2] = run;
    }
    __syncthreads();
    int i = blockIdx.x * 256 + t;
    if (i < NG2) {
        int ex = boff[i >> 10] + g_gscan[i] - g_gmax[i];
        g_gbase[i] = ex * ILV;
    }
    if (i == 0) g_gbase[NG2] = boff[NGB2] * ILV;
    if (i < NN) {
        int r = g_rank[i];
        int g = r >> 4;
        int gm = g_gmax[g];
        int base = (boff[g >> 10] + g_gscan[g] - gm) * ILV;
        int sb = base + (r & 15);
        g_sbc[i].y = sb;
        int deg = g_cnt[i];
        for (int k = deg; k < gm; k++) g_eil[sb + k * ILV] = NN;  // precise pad
    }
}

__global__ void k_scatter2(const int* __restrict__ ei) {  // 4 edges per thread
    int e4 = blockIdx.x * 256 + threadIdx.x;
    if (e4 < EE / 4) {
        int4 s = ((const int4*)ei)[e4];
        int4 d = ((const int4*)(ei + EE))[e4];
#pragma unroll
        for (int q = 0; q < 4; q++) {
            int ss = (q == 0) ? s.x : (q == 1) ? s.y : (q == 2) ? s.z : s.w;
            int dd = (q == 0) ? d.x : (q == 1) ? d.y : (q == 2) ? d.z : d.w;
            int i = atomicAdd(&g_sbc[dd].x, 1);
            int sb = g_sbc[dd].y;
            g_eil[sb + i * ILV] = g_rank[ss];
        }
    }
}

// -------- first transform: g_hA[rank(n)] = dis[n] * (x[n] @ w_in) --------
__global__ __launch_bounds__(256) void k_xw(const float* __restrict__ x,
                                            const float* __restrict__ w) {
    __shared__ float xs[16 * 128];
    __shared__ float ws[128 * 16];
    int t = threadIdx.x;
    for (int i = t; i < 512; i += 256) ((float4*)ws)[i] = ((const float4*)w)[i];
    const float4* xb = (const float4*)(x + (size_t)blockIdx.x * 2048);
    for (int i = t; i < 512; i += 256) ((float4*)xs)[i] = xb[i];
    __syncthreads();
    int ry = t >> 4, c = t & 15;
    float s = 0.f;
#pragma unroll
    for (int k = 0; k < 128; k++) s = fmaf(xs[ry * 128 + k], ws[k * 16 + c], s);
    int node = blockIdx.x * 16 + ry;
    g_hA[(size_t)g_rank[node] * 16 + c] = __float2half_rn(s * g_dis[node]);
}

// ---------------- cp.async helpers ----------------
__device__ __forceinline__ void cp16(unsigned smem, const void* gptr) {
    asm volatile("cp.async.cg.shared.global [%0], [%1], 16;"
                 :: "r"(smem), "l"(gptr) : "memory");
}
__device__ __forceinline__ void cp_commit() {
    asm volatile("cp.async.commit_group;" ::: "memory");
}
template <int N>
__device__ __forceinline__ void cp_wait() {
    asm volatile("cp.async.wait_group %0;" :: "n"(N) : "memory");
}

__device__ __forceinline__ void h8_init(float* a, uint4 v) {
    __half2* h = (__half2*)&v;
#pragma unroll
    for (int q = 0; q < 4; q++) {
        float2 f = __half22float2(h[q]);
        a[2 * q] = f.x; a[2 * q + 1] = f.y;
    }
}
__device__ __forceinline__ void h8_add(float* a, uint4 v) {
    __half2* h = (__half2*)&v;
#pragma unroll
    for (int q = 0; q < 4; q++) {
        float2 f = __half22float2(h[q]);
        a[2 * q] += f.x; a[2 * q + 1] += f.y;
    }
}
__device__ __forceinline__ uint4 f8_to_h8(const float* a) {
    uint4 r;
    __half2* h = (__half2*)&r;
#pragma unroll
    for (int q = 0; q < 4; q++) h[q] = __floats2half2_rn(a[2 * q], a[2 * q + 1]);
    return r;
}

// ---------------- fused aggregation layers (cp.async gather pipeline) -------
// MODE 0: h = relu(dis*agg+b); store dis*(h @ Wn)    [8x]
// MODE 1: store dis*relu(dis*agg+b)                   [h9]
// MODE 2: o = (dis*agg) @ w_out + b_out; log_softmax  [final]
template <int MODE>
__global__ __launch_bounds__(256) void k_agg(int inA,
                                             const float* __restrict__ preBias,
                                             const float* __restrict__ Wn,
                                             const float* __restrict__ postBias,
                                             float* __restrict__ fout) {
    __shared__ uint4 stage[8][DEPTH][32];
    __shared__ float wsh[640];
    __shared__ float bsh[40];
    __shared__ float hsh[128 * 17];
    int t = threadIdx.x;
    if (MODE == 0) wsh[t] = Wn[t & 255];
    if (MODE == 2) {
        for (int i = t; i < 640; i += 256) wsh[i] = Wn[i];
        if (t < 40) bsh[t] = postBias[t];
    }
    __syncthreads();

    int w = t >> 5, lane = t & 31;
    // block-level degree swizzle: spreads degree-sorted work across SMs/waves
    int b = (int)(((long long)blockIdx.x * BPERM) % NBA);
    int gw = b * 8 + w;
    if (gw >= NG2) return;

    const uint4* tab = (const uint4*)(inA ? g_hA : g_hB);
    __half* outF = inA ? g_hB : g_hA;

    int j = lane >> 1, h = lane & 1;
    int row = gw * ILV + j;            // rank-ordered feature row
    float di = g_disP[row];

    float acc[8];
    h8_init(acc, __ldg(&tab[row * 2 + h]));   // self loop (coalesced)

    int base = g_gbase[gw];
    int nch = (g_gbase[gw + 1] - base) >> 4;
    const int* eilc = g_eil + base + j;
    unsigned sa0 = (unsigned)__cvta_generic_to_shared(&stage[w][0][lane]);

    int npro = nch < DEPTH ? nch : DEPTH;
    for (int c = 0; c < npro; c++) {
        int src = __ldg(eilc + c * ILV);
        cp16(sa0 + (c & (DEPTH - 1)) * 512, tab + src * 2 + h);
        cp_commit();
    }
    int c = 0;
    // steady state: consume 2 chunks per wait, issue 2
    for (; c + DEPTH + 1 < nch; c += 2) {
        cp_wait<DEPTH - 2>();                       // chunks c, c+1 ready
        h8_add(acc, stage[w][c & (DEPTH - 1)][lane]);
        h8_add(acc, stage[w][(c + 1) & (DEPTH - 1)][lane]);
        int c0 = c + DEPTH, c1 = c + DEPTH + 1;
        int s0 = __ldg(eilc + c0 * ILV);
        int s1 = __ldg(eilc + c1 * ILV);
        cp16(sa0 + (c0 & (DEPTH - 1)) * 512, tab + s0 * 2 + h);
        cp_commit();
        cp16(sa0 + (c1 & (DEPTH - 1)) * 512, tab + s1 * 2 + h);
        cp_commit();
    }
    cp_wait<0>();
    for (; c < nch; c++) h8_add(acc, stage[w][c & (DEPTH - 1)][lane]);

#pragma unroll
    for (int q = 0; q < 8; q++) acc[q] *= di;

    if (MODE != 2) {  // bias + relu
        const float* bp = preBias + h * 8;
#pragma unroll
        for (int q = 0; q < 8; q++) acc[q] = fmaxf(acc[q] + __ldg(bp + q), 0.f);
    }

    if (MODE == 1) {  // store dis*h (coalesced, rank order)
#pragma unroll
        for (int q = 0; q < 8; q++) acc[q] *= di;
        ((uint4*)outF)[row * 2 + h] = f8_to_h8(acc);
        return;
    }

    // share the node's 16-vector between its 2 lanes
    float* hr = &hsh[(t >> 1) * 17];
#pragma unroll
    for (int q = 0; q < 8; q++) hr[h * 8 + q] = acc[q];
    __syncwarp();

    if (MODE == 0) {  // 16x16 transform, store pre-scaled by dis
        float o[8];
#pragma unroll
        for (int jj = 0; jj < 8; jj++) {
            int col = h * 8 + jj;
            float s = 0.f;
#pragma unroll
            for (int k = 0; k < 16; k++) s = fmaf(hr[k], wsh[k * 16 + col], s);
            o[jj] = s * di;
        }
        ((uint4*)outF)[row * 2 + h] = f8_to_h8(o);
    } else {  // MODE 2: 16x40 output transform + log_softmax
        float o[20];
#pragma unroll
        for (int jj = 0; jj < 20; jj++) {
            int col = h * 20 + jj;
            float s = bsh[col];
#pragma unroll
            for (int k = 0; k < 16; k++) s = fmaf(hr[k], wsh[k * 40 + col], s);
            o[jj] = s;
        }
        float m = o[0];
#pragma unroll
        for (int jj = 1; jj < 20; jj++) m = fmaxf(m, o[jj]);
        m = fmaxf(m, __shfl_xor_sync(0xffffffffu, m, 1));
        float se = 0.f;
#pragma unroll
        for (int jj = 0; jj < 20; jj++) se += __expf(o[jj] - m);
        se += __shfl_xor_sync(0xffffffffu, se, 1);
        float l = m + __logf(se);
        int node = g_order[row];
#pragma unroll
        for (int jj = 0; jj < 20; jj++)
            fout[(size_t)node * 40 + h * 20 + jj] = o[jj] - l;
    }
}

// ---------------- launch ----------------
extern "C" void kernel_launch(void* const* d_in, const int* in_sizes, int n_in,
                              void* d_out, int out_size) {
    const float* x     = (const float*)d_in[0];
    const float* w_in  = (const float*)d_in[1];
    const float* b_in  = (const float*)d_in[2];
    const float* w_hid = (const float*)d_in[3];
    const float* b_hid = (const float*)d_in[4];
    const float* w_out = (const float*)d_in[5];
    const float* b_out = (const float*)d_in[6];
    const int*   ei    = (const int*)d_in[7];
    float* out = (float*)d_out;

    const int NB_N = (NN + 255) / 256;       // 782
    const int NB_E4 = (EE / 4 + 255) / 256;  // 6250

    // zero scratch via DMA memsets
    void *p_cnt, *p_sbc, *p_dbin, *p_dcur;
    cudaGetSymbolAddress(&p_cnt, g_cnt);
    cudaGetSymbolAddress(&p_sbc, g_sbc);
    cudaGetSymbolAddress(&p_dbin, g_dbin);
    cudaGetSymbolAddress(&p_dcur, g_dcur);
    cudaMemsetAsync(p_cnt, 0, NN * sizeof(int));
    cudaMemsetAsync(p_sbc, 0, NN * sizeof(int2));
    cudaMemsetAsync(p_dbin, 0, NBIN * sizeof(int));
    cudaMemsetAsync(p_dcur, 0, NBIN * sizeof(int));

    // prep chain on the capture stream
    k_hist<<<NB_E4, 256>>>(ei);
    k_dhist<<<NB_N, 256>>>();
    k_dplace<<<NB_N, 256>>>();

    // fork: k_xw (HBM-bound, needs only g_rank/g_dis) runs concurrently with
    // the ELL build (L2/atomic-bound). Stream/event create+destroy execute
    // host-side during capture only; replays run the captured graph.
    cudaStream_t s2;
    cudaStreamCreate(&s2);
    cudaEvent_t evFork, evJoin;
    cudaEventCreateWithFlags(&evFork, cudaEventDisableTiming);
    cudaEventCreateWithFlags(&evJoin, cudaEventDisableTiming);
    cudaEventRecord(evFork, 0);
    cudaStreamWaitEvent(s2, evFork, 0);
    k_xw<<<NN / 16, 256, 0, s2>>>(x, w_in);
    cudaEventRecord(evJoin, s2);

    k_gmaxscan<<<NGB2, 1024>>>();
    k_sbpad<<<NB_N, 256>>>();
    k_scatter2<<<NB_E4, 256>>>(ei);

    cudaStreamWaitEvent(0, evJoin, 0);
    cudaEventDestroy(evFork);
    cudaEventDestroy(evJoin);
    cudaStreamDestroy(s2);

    // layers 1..8: fused agg + bias + relu + next 16x16 transform (ping-pong)
    k_agg<0><<<NBA, 256>>>(1, b_in,         w_hid + 0 * 256, nullptr, nullptr);
    k_agg<0><<<NBA, 256>>>(0, b_hid + 0*16, w_hid + 1 * 256, nullptr, nullptr);
    k_agg<0><<<NBA, 256>>>(1, b_hid + 1*16, w_hid + 2 * 256, nullptr, nullptr);
    k_agg<0><<<NBA, 256>>>(0, b_hid + 2*16, w_hid + 3 * 256, nullptr, nullptr);
    k_agg<0><<<NBA, 256>>>(1, b_hid + 3*16, w_hid + 4 * 256, nullptr, nullptr);
    k_agg<0><<<NBA, 256>>>(0, b_hid + 4*16, w_hid + 5 * 256, nullptr, nullptr);
    k_agg<0><<<NBA, 256>>>(1, b_hid + 5*16, w_hid + 6 * 256, nullptr, nullptr);
    k_agg<0><<<NBA, 256>>>(0, b_hid + 6*16, w_hid + 7 * 256, nullptr, nullptr);
    // layer 9: h9-hat (hA -> hB)
    k_agg<1><<<NBA, 256>>>(1, b_hid + 7*16, nullptr, nullptr, nullptr);
    // layer 10: out = log_softmax((dis*agg(h9-hat)) @ w_out + b_out)
    k_agg<2><<<NBA, 256>>>(0, nullptr, w_out, b_out, out);
}